// round 15
// baseline (speedup 1.0000x reference)
#include <cuda_runtime.h>
#include <cuda_fp16.h>
#include <math.h>
#include <stdint.h>

// ---------------------------------------------------------------------------
// Problem constants
// ---------------------------------------------------------------------------
#define D_MODEL   1024
#define N_HEADS   16
#define N_KV      8
#define HEAD_DIM  64
#define HIDDEN    4096
#define BATCH     4
#define SEQ       2048
#define BT        (BATCH * SEQ)
#define QKV_N     2048

// ---------------------------------------------------------------------------
// Scratch (device globals)
// ---------------------------------------------------------------------------
__device__ __half g_h  [BT * D_MODEL];
__device__ __half g_qh [BT * D_MODEL];
__device__ __half g_kh [BT * N_KV * HEAD_DIM];
__device__ __half g_vh [BT * N_KV * HEAD_DIM];
__device__ __half g_ao [BT * D_MODEL];
__device__ __half g_h2 [BT * D_MODEL];
__device__ __half g_a2 [BT * HIDDEN];
__device__ float2 g_rope[SEQ * 32];

__device__ __half g_wqkvT[QKV_N * D_MODEL];
__device__ __half g_woT [D_MODEL * D_MODEL];
__device__ __half g_w12T[2 * HIDDEN * D_MODEL];
__device__ __half g_w3T [D_MODEL * HIDDEN];

// ---------------------------------------------------------------------------
// Helpers
// ---------------------------------------------------------------------------
__device__ __forceinline__ void mma_f16(float* c, const uint32_t* a, const uint32_t* b) {
    asm volatile(
        "mma.sync.aligned.m16n8k16.row.col.f32.f16.f16.f32 "
        "{%0,%1,%2,%3}, {%4,%5,%6,%7}, {%8,%9}, {%0,%1,%2,%3};\n"
        : "+f"(c[0]), "+f"(c[1]), "+f"(c[2]), "+f"(c[3])
        : "r"(a[0]), "r"(a[1]), "r"(a[2]), "r"(a[3]), "r"(b[0]), "r"(b[1]));
}
__device__ __forceinline__ void ldm_x4(uint32_t* d, uint32_t saddr) {
    asm volatile(
        "ldmatrix.sync.aligned.m8n8.x4.shared.b16 {%0,%1,%2,%3}, [%4];"
        : "=r"(d[0]), "=r"(d[1]), "=r"(d[2]), "=r"(d[3]) : "r"(saddr));
}
__device__ __forceinline__ void ldm_x4_t(uint32_t* d, uint32_t saddr) {
    asm volatile(
        "ldmatrix.sync.aligned.m8n8.x4.trans.shared.b16 {%0,%1,%2,%3}, [%4];"
        : "=r"(d[0]), "=r"(d[1]), "=r"(d[2]), "=r"(d[3]) : "r"(saddr));
}
__device__ __forceinline__ uint32_t cvta_s(const void* p) {
    return (uint32_t)__cvta_generic_to_shared(p);
}
__device__ __forceinline__ void cp16(uint32_t dst, const void* src) {
    asm volatile(
        "{ .reg .u64 g; cvta.to.global.u64 g, %1; "
        "cp.async.cg.shared.global [%0], [g], 16; }"
        :: "r"(dst), "l"(src) : "memory");
}
#define CP_COMMIT() asm volatile("cp.async.commit_group;\n" ::: "memory")
#define CP_WAIT1()  asm volatile("cp.async.wait_group 1;\n" ::: "memory")
#define CP_WAIT0()  asm volatile("cp.async.wait_group 0;\n" ::: "memory")

__device__ __forceinline__ uint32_t h2_u32(__half2 h) {
    uint32_t u;
    *reinterpret_cast<__half2*>(&u) = h;
    return u;
}

#define EPI_RES    1
#define EPI_HALF   2
#define EPI_ROPE   4
#define EPI_SWIGLU 5

// ---------------------------------------------------------------------------
// fp16 tensor-core GEMM; mainloop unchanged; R15: 3 CTAs/SM
// ---------------------------------------------------------------------------
#define BKH   32
#define LDH   40
#define STG_H (128 * LDH)
#define GEMM_SMEM_BYTES (6 * STG_H * 2)

__global__ void __launch_bounds__(128, 3)
hgemm(const __half* __restrict__ A, const __half* __restrict__ Bt,
      const void* __restrict__ Rv, void* __restrict__ Cv,
      int M, int N, int K, int epi,
      __half* __restrict__ q_out, __half* __restrict__ k_out,
      __half* __restrict__ v_out, const float2* __restrict__ rope_tab) {
    extern __shared__ __half smh[];
    __half* Abuf[3] = { smh, smh + 2 * STG_H, smh + 4 * STG_H };
    __half* Bbuf[3] = { smh + STG_H, smh + 3 * STG_H, smh + 5 * STG_H };

    const int tid  = threadIdx.x;
    const int wid  = tid >> 5;
    const int lane = tid & 31;
    const int wm   = wid >> 1;
    const int wn   = wid & 1;
    const int gr   = lane >> 2;
    const int gc   = lane & 3;
    const int m0 = blockIdx.y << 7;
    const int n0 = blockIdx.x << 7;

    const int lr = tid >> 2;
    const int lc = (tid & 3) << 3;
    const __half* Ag = A  + (long)(m0 + lr) * K + lc;
    const __half* Bg = Bt + (long)(n0 + lr) * K + lc;

    uint32_t sA[3], sB[3], sAb[3], sBb[3];
    #pragma unroll
    for (int s = 0; s < 3; s++) {
        sAb[s] = cvta_s(Abuf[s]);
        sBb[s] = cvta_s(Bbuf[s]);
        sA[s] = cvta_s(&Abuf[s][lr * LDH + lc]);
        sB[s] = cvta_s(&Bbuf[s][lr * LDH + lc]);
    }
    const uint32_t rowstep = 32 * LDH * 2;

    const int l7  = lane & 7;
    const int sel = lane >> 3;
    const uint32_t aOff = (uint32_t)(((wm * 64 + l7 + (sel & 1) * 8) * LDH + (sel >> 1) * 8) * 2);
    const uint32_t bOff = (uint32_t)(((wn * 64 + l7 + (sel >> 1) * 8) * LDH + (sel & 1) * 8) * 2);

    const int NC = K / BKH;

    float acc[4][8][4];
    #pragma unroll
    for (int i = 0; i < 4; i++)
        #pragma unroll
        for (int j = 0; j < 8; j++)
            #pragma unroll
            for (int q = 0; q < 4; q++) acc[i][j][q] = 0.f;

    #pragma unroll
    for (int c0i = 0; c0i < 2; c0i++) {
        const long ko = (long)c0i * BKH;
        #pragma unroll
        for (int p = 0; p < 4; p++) {
            cp16(sA[c0i] + p * rowstep, Ag + (long)(p * 32) * K + ko);
            cp16(sB[c0i] + p * rowstep, Bg + (long)(p * 32) * K + ko);
        }
        CP_COMMIT();
    }

    for (int i = 0; i < NC; i++) {
        if (i < NC - 1) CP_WAIT1(); else CP_WAIT0();
        __syncthreads();

        if (i + 2 < NC) {
            const int s2 = (i + 2) % 3;
            const long ko = (long)(i + 2) * BKH;
            #pragma unroll
            for (int p = 0; p < 4; p++) {
                cp16(sA[s2] + p * rowstep, Ag + (long)(p * 32) * K + ko);
                cp16(sB[s2] + p * rowstep, Bg + (long)(p * 32) * K + ko);
            }
            CP_COMMIT();
        }

        const int cur = i % 3;
        const uint32_t aBase = sAb[cur] + aOff;
        const uint32_t bBase = sBb[cur] + bOff;

        #pragma unroll
        for (int ks = 0; ks < 2; ks++) {
            const uint32_t kb = (uint32_t)(ks * 16 * 2);
            uint32_t af[4][4], bf[8][2];
            #pragma unroll
            for (int mt = 0; mt < 4; mt++)
                ldm_x4(af[mt], aBase + (uint32_t)(mt * 16 * LDH * 2) + kb);
            #pragma unroll
            for (int np = 0; np < 4; np++) {
                uint32_t d[4];
                ldm_x4(d, bBase + (uint32_t)(np * 16 * LDH * 2) + kb);
                bf[np * 2][0]     = d[0]; bf[np * 2][1]     = d[1];
                bf[np * 2 + 1][0] = d[2]; bf[np * 2 + 1][1] = d[3];
            }
            #pragma unroll
            for (int mt = 0; mt < 4; mt++)
                #pragma unroll
                for (int nt = 0; nt < 8; nt++)
                    mma_f16(acc[mt][nt], af[mt], bf[nt]);
        }
    }
    __syncthreads();

    // ---------------- epilogues ----------------
    if (epi == EPI_ROPE) {
        const int head = (n0 + wn * 64) >> 6;
        #pragma unroll
        for (int mt = 0; mt < 4; mt++) {
            const int rowA = m0 + wm * 64 + mt * 16 + gr;
            const int rowB = rowA + 8;
            const int tA = rowA & (SEQ - 1);
            const int tB = rowB & (SEQ - 1);
            if (head < 24) {
                __half* dstA;
                long stride;
                if (head < 16) {
                    dstA = q_out + (long)rowA * D_MODEL + head * HEAD_DIM;
                    stride = D_MODEL;
                } else {
                    dstA = k_out + (long)rowA * (N_KV * HEAD_DIM) + (head - 16) * HEAD_DIM;
                    stride = N_KV * HEAD_DIM;
                }
                __half* dstB = dstA + 8 * stride;
                #pragma unroll
                for (int nt = 0; nt < 4; nt++) {
                    const int j0 = nt * 8 + gc * 2;
                    const float2 cA0 = rope_tab[tA * 32 + j0];
                    const float2 cA1 = rope_tab[tA * 32 + j0 + 1];
                    const float2 cB0 = rope_tab[tB * 32 + j0];
                    const float2 cB1 = rope_tab[tB * 32 + j0 + 1];
                    const float x1a0 = acc[mt][nt][0],     x1a1 = acc[mt][nt][1];
                    const float x1b0 = acc[mt][nt][2],     x1b1 = acc[mt][nt][3];
                    const float x2a0 = acc[mt][nt + 4][0], x2a1 = acc[mt][nt + 4][1];
                    const float x2b0 = acc[mt][nt + 4][2], x2b1 = acc[mt][nt + 4][3];
                    *reinterpret_cast<__half2*>(dstA + j0) =
                        __floats2half2_rn(x1a0 * cA0.x - x2a0 * cA0.y,
                                          x1a1 * cA1.x - x2a1 * cA1.y);
                    *reinterpret_cast<__half2*>(dstA + j0 + 32) =
                        __floats2half2_rn(x2a0 * cA0.x + x1a0 * cA0.y,
                                          x2a1 * cA1.x + x1a1 * cA1.y);
                    *reinterpret_cast<__half2*>(dstB + j0) =
                        __floats2half2_rn(x1b0 * cB0.x - x2b0 * cB0.y,
                                          x1b1 * cB1.x - x2b1 * cB1.y);
                    *reinterpret_cast<__half2*>(dstB + j0 + 32) =
                        __floats2half2_rn(x2b0 * cB0.x + x1b0 * cB0.y,
                                          x2b1 * cB1.x + x1b1 * cB1.y);
                }
            } else {
                __half* dstA = v_out + (long)rowA * (N_KV * HEAD_DIM) + (head - 24) * HEAD_DIM;
                __half* dstB = dstA + 8 * (N_KV * HEAD_DIM);
                #pragma unroll
                for (int nt = 0; nt < 8; nt++) {
                    const int c = nt * 8 + gc * 2;
                    *reinterpret_cast<__half2*>(dstA + c) =
                        __floats2half2_rn(acc[mt][nt][0], acc[mt][nt][1]);
                    *reinterpret_cast<__half2*>(dstB + c) =
                        __floats2half2_rn(acc[mt][nt][2], acc[mt][nt][3]);
                }
            }
        }
        return;
    }

    if (epi == EPI_SWIGLU) {
        __half* C = (__half*)Cv;
        const int NH = N >> 1;
        #pragma unroll
        for (int mt = 0; mt < 4; mt++) {
            #pragma unroll
            for (int nt = 0; nt < 8; nt++) {
                const int row = m0 + wm * 64 + mt * 16 + gr;
                const int jcol = ((n0 + wn * 64 + nt * 8) >> 1) + gc;
                const float aA = acc[mt][nt][0], bA = acc[mt][nt][1];
                const float aB = acc[mt][nt][2], bB = acc[mt][nt][3];
                C[(long)row * NH + jcol] =
                    __float2half_rn(aA / (1.0f + __expf(-aA)) * bA);
                C[(long)(row + 8) * NH + jcol] =
                    __float2half_rn(aB / (1.0f + __expf(-aB)) * bB);
            }
        }
        return;
    }

    #pragma unroll
    for (int mt = 0; mt < 4; mt++) {
        #pragma unroll
        for (int nt = 0; nt < 8; nt++) {
            const int row = m0 + wm * 64 + mt * 16 + gr;
            const int col = n0 + wn * 64 + nt * 8 + gc * 2;
            const long offA = (long)row * N + col;
            const long offB = (long)(row + 8) * N + col;
            float2 lo = make_float2(acc[mt][nt][0], acc[mt][nt][1]);
            float2 hi = make_float2(acc[mt][nt][2], acc[mt][nt][3]);
            if (epi == EPI_RES) {
                const float* R = (const float*)Rv;
                float2 r0 = *reinterpret_cast<const float2*>(R + offA);
                float2 r1 = *reinterpret_cast<const float2*>(R + offB);
                lo.x += r0.x; lo.y += r0.y;
                hi.x += r1.x; hi.y += r1.y;
                *reinterpret_cast<float2*>((float*)Cv + offA) = lo;
                *reinterpret_cast<float2*>((float*)Cv + offB) = hi;
            } else {  // EPI_HALF
                *reinterpret_cast<__half2*>((__half*)Cv + offA) = __floats2half2_rn(lo.x, lo.y);
                *reinterpret_cast<__half2*>((__half*)Cv + offB) = __floats2half2_rn(hi.x, hi.y);
            }
        }
    }
}

// ---------------------------------------------------------------------------
// fp16 flash attention, causal GQA (R12 version: 128 threads, 4 warps x 32 rows)
// ---------------------------------------------------------------------------
#define QS_LDH 72
#define KS_LDH 72
#define VS_LDH 72
#define ATTN_SMEM ((128 * QS_LDH + 2 * 64 * KS_LDH + 2 * 64 * VS_LDH) * 2)

__global__ void __launch_bounds__(128, 2)
attn_h(const __half* __restrict__ qh, const __half* __restrict__ kh,
       const __half* __restrict__ vh, __half* __restrict__ o) {
    extern __shared__ __half smh[];
    __half* Qs = smh;
    __half* Kb[2] = { smh + 128 * QS_LDH, smh + 128 * QS_LDH + 64 * KS_LDH };
    __half* Vb[2] = { Kb[1] + 64 * KS_LDH, Kb[1] + 64 * KS_LDH + 64 * VS_LDH };

    const int tid  = threadIdx.x;
    const int warp = tid >> 5;
    const int lane = tid & 31;
    const int gr = lane >> 2;
    const int gc = lane & 3;
    const int wr = warp << 5;

    const int t0  = blockIdx.x << 7;
    const int bh  = blockIdx.y;
    const int b   = bh >> 4;
    const int hq  = bh & 15;
    const int kvh = hq >> 1;

    const uint32_t qsb = cvta_s(Qs);
    uint32_t ksb[2] = { cvta_s(Kb[0]), cvta_s(Kb[1]) };
    uint32_t vsb[2] = { cvta_s(Vb[0]), cvta_s(Vb[1]) };

    const int l7  = lane & 7;
    const int sel = lane >> 3;
    const uint32_t aQoff = (uint32_t)(((wr + l7 + (sel & 1) * 8) * QS_LDH + (sel >> 1) * 8) * 2);
    const uint32_t bKoff = (uint32_t)(((l7 + (sel >> 1) * 8) * KS_LDH + (sel & 1) * 8) * 2);
    const uint32_t vToff = (uint32_t)((((sel & 1) * 8 + l7) * VS_LDH + (sel >> 1) * 8) * 2);

    const int ldr = tid >> 3;
    const int ldc = (tid & 7) << 3;

    {
        #pragma unroll
        for (int p = 0; p < 8; p++) {
            const int row = ldr + p * 16;
            cp16(qsb + (uint32_t)((row * QS_LDH + ldc) * 2),
                 qh + (long)(b * SEQ + t0 + row) * D_MODEL + hq * HEAD_DIM + ldc);
        }
    }
    {
        #pragma unroll
        for (int p = 0; p < 4; p++) {
            const int row = ldr + p * 16;
            const long base = (long)(b * SEQ + row) * (N_KV * HEAD_DIM) + kvh * HEAD_DIM + ldc;
            cp16(ksb[0] + (uint32_t)((row * KS_LDH + ldc) * 2), kh + base);
            cp16(vsb[0] + (uint32_t)((row * VS_LDH + ldc) * 2), vh + base);
        }
        CP_COMMIT();
    }

    float ofrag[2][8][4];
    #pragma unroll
    for (int mt = 0; mt < 2; mt++)
        #pragma unroll
        for (int nt = 0; nt < 8; nt++)
            #pragma unroll
            for (int r = 0; r < 4; r++) ofrag[mt][nt][r] = 0.f;

    float mrow[2][2] = {{-1e30f, -1e30f}, {-1e30f, -1e30f}};
    float lrow[2][2] = {{0.f, 0.f}, {0.f, 0.f}};
    const float SC = 0.125f;

    const int ntiles = (t0 >> 6) + 2;
    for (int it = 0; it < ntiles; it++) {
        const int s0 = it << 6;
        const int cur = it & 1;

        if (it + 1 < ntiles) {
            const int nxt = cur ^ 1;
            const long roff = (long)((it + 1) << 6) * (N_KV * HEAD_DIM);
            #pragma unroll
            for (int p = 0; p < 4; p++) {
                const int row = ldr + p * 16;
                const long base = (long)(b * SEQ + row) * (N_KV * HEAD_DIM) + kvh * HEAD_DIM + ldc + roff;
                cp16(ksb[nxt] + (uint32_t)((row * KS_LDH + ldc) * 2), kh + base);
                cp16(vsb[nxt] + (uint32_t)((row * VS_LDH + ldc) * 2), vh + base);
            }
            CP_COMMIT();
            CP_WAIT1();
        } else {
            CP_WAIT0();
        }
        __syncthreads();

        float sfrag[2][8][4];
        #pragma unroll
        for (int mt = 0; mt < 2; mt++)
            #pragma unroll
            for (int nt = 0; nt < 8; nt++)
                #pragma unroll
                for (int r = 0; r < 4; r++) sfrag[mt][nt][r] = 0.f;

        #pragma unroll
        for (int ks = 0; ks < 4; ks++) {
            const uint32_t kb = (uint32_t)(ks * 16 * 2);
            uint32_t aq[2][4], bk[8][2];
            #pragma unroll
            for (int mt = 0; mt < 2; mt++)
                ldm_x4(aq[mt], qsb + aQoff + (uint32_t)(mt * 16 * QS_LDH * 2) + kb);
            #pragma unroll
            for (int np = 0; np < 4; np++) {
                uint32_t d[4];
                ldm_x4(d, ksb[cur] + bKoff + (uint32_t)(np * 16 * KS_LDH * 2) + kb);
                bk[np * 2][0]     = d[0]; bk[np * 2][1]     = d[1];
                bk[np * 2 + 1][0] = d[2]; bk[np * 2 + 1][1] = d[3];
            }
            #pragma unroll
            for (int mt = 0; mt < 2; mt++)
                #pragma unroll
                for (int nt = 0; nt < 8; nt++)
                    mma_f16(sfrag[mt][nt], aq[mt], bk[nt]);
        }

        if (it >= ntiles - 2) {
            #pragma unroll
            for (int mt = 0; mt < 2; mt++) {
                const int rA = t0 + wr + mt * 16 + gr;
                const int rB = rA + 8;
                #pragma unroll
                for (int nt = 0; nt < 8; nt++) {
                    const int cb = s0 + nt * 8 + 2 * gc;
                    if (cb     > rA) sfrag[mt][nt][0] = -1e30f;
                    if (cb + 1 > rA) sfrag[mt][nt][1] = -1e30f;
                    if (cb     > rB) sfrag[mt][nt][2] = -1e30f;
                    if (cb + 1 > rB) sfrag[mt][nt][3] = -1e30f;
                }
            }
        }

        #pragma unroll
        for (int mt = 0; mt < 2; mt++) {
            float r0 = -1e30f, r1 = -1e30f;
            #pragma unroll
            for (int nt = 0; nt < 8; nt++) {
                r0 = fmaxf(r0, fmaxf(sfrag[mt][nt][0], sfrag[mt][nt][1]));
                r1 = fmaxf(r1, fmaxf(sfrag[mt][nt][2], sfrag[mt][nt][3]));
            }
            r0 = fmaxf(r0, __shfl_xor_sync(0xffffffffu, r0, 1));
            r0 = fmaxf(r0, __shfl_xor_sync(0xffffffffu, r0, 2));
            r1 = fmaxf(r1, __shfl_xor_sync(0xffffffffu, r1, 1));
            r1 = fmaxf(r1, __shfl_xor_sync(0xffffffffu, r1, 2));

            const float mn0 = fmaxf(mrow[mt][0], r0);
            const float mn1 = fmaxf(mrow[mt][1], r1);
            const float c0 = __expf((mrow[mt][0] - mn0) * SC);
            const float c1 = __expf((mrow[mt][1] - mn1) * SC);
            lrow[mt][0] *= c0;
            lrow[mt][1] *= c1;
            #pragma unroll
            for (int nt = 0; nt < 8; nt++) {
                ofrag[mt][nt][0] *= c0; ofrag[mt][nt][1] *= c0;
                ofrag[mt][nt][2] *= c1; ofrag[mt][nt][3] *= c1;
            }
            float s0s = 0.f, s1s = 0.f;
            #pragma unroll
            for (int nt = 0; nt < 8; nt++) {
                sfrag[mt][nt][0] = __expf((sfrag[mt][nt][0] - mn0) * SC);
                sfrag[mt][nt][1] = __expf((sfrag[mt][nt][1] - mn0) * SC);
                sfrag[mt][nt][2] = __expf((sfrag[mt][nt][2] - mn1) * SC);
                sfrag[mt][nt][3] = __expf((sfrag[mt][nt][3] - mn1) * SC);
                s0s += sfrag[mt][nt][0] + sfrag[mt][nt][1];
                s1s += sfrag[mt][nt][2] + sfrag[mt][nt][3];
            }
            s0s += __shfl_xor_sync(0xffffffffu, s0s, 1);
            s0s += __shfl_xor_sync(0xffffffffu, s0s, 2);
            s1s += __shfl_xor_sync(0xffffffffu, s1s, 1);
            s1s += __shfl_xor_sync(0xffffffffu, s1s, 2);
            lrow[mt][0] += s0s;
            lrow[mt][1] += s1s;
            mrow[mt][0] = mn0;
            mrow[mt][1] = mn1;
        }

        #pragma unroll
        for (int ks = 0; ks < 4; ks++) {
            uint32_t ap[2][4];
            #pragma unroll
            for (int mt = 0; mt < 2; mt++) {
                ap[mt][0] = h2_u32(__floats2half2_rn(sfrag[mt][2 * ks][0],     sfrag[mt][2 * ks][1]));
                ap[mt][1] = h2_u32(__floats2half2_rn(sfrag[mt][2 * ks][2],     sfrag[mt][2 * ks][3]));
                ap[mt][2] = h2_u32(__floats2half2_rn(sfrag[mt][2 * ks + 1][0], sfrag[mt][2 * ks + 1][1]));
                ap[mt][3] = h2_u32(__floats2half2_rn(sfrag[mt][2 * ks + 1][2], sfrag[mt][2 * ks + 1][3]));
            }
            uint32_t bv[8][2];
            #pragma unroll
            for (int np = 0; np < 4; np++) {
                uint32_t d[4];
                ldm_x4_t(d, vsb[cur] + vToff +
                            (uint32_t)((ks * 16 * VS_LDH + np * 16) * 2));
                bv[np * 2][0]     = d[0]; bv[np * 2][1]     = d[1];
                bv[np * 2 + 1][0] = d[2]; bv[np * 2 + 1][1] = d[3];
            }
            #pragma unroll
            for (int mt = 0; mt < 2; mt++)
                #pragma unroll
                for (int nt = 0; nt < 8; nt++)
                    mma_f16(ofrag[mt][nt], ap[mt], bv[nt]);
        }
        __syncthreads();
    }

    #pragma unroll
    for (int mt = 0; mt < 2; mt++) {
        const int rowA = t0 + wr + mt * 16 + gr;
        const int rowB = rowA + 8;
        const float il0 = 1.0f / lrow[mt][0];
        const float il1 = 1.0f / lrow[mt][1];
        #pragma unroll
        for (int nt = 0; nt < 8; nt++) {
            const int col = hq * HEAD_DIM + nt * 8 + 2 * gc;
            *reinterpret_cast<__half2*>(o + (long)(b * SEQ + rowA) * D_MODEL + col) =
                __floats2half2_rn(ofrag[mt][nt][0] * il0, ofrag[mt][nt][1] * il0);
            *reinterpret_cast<__half2*>(o + (long)(b * SEQ + rowB) * D_MODEL + col) =
                __floats2half2_rn(ofrag[mt][nt][2] * il1, ofrag[mt][nt][3] * il1);
        }
    }
}

// ---------------------------------------------------------------------------
// Transpose to half: out[(c*stride + roff)*R + r] = in[r*C + c]
// ---------------------------------------------------------------------------
__global__ void transpose_h(const float* __restrict__ in,
                            __half* __restrict__ out, int R, int C,
                            int stride, int roff) {
    __shared__ float t[32][33];
    const int c0 = blockIdx.x << 5, r0 = blockIdx.y << 5;
    #pragma unroll
    for (int dy = 0; dy < 32; dy += 8) {
        t[threadIdx.y + dy][threadIdx.x] =
            in[(long)(r0 + threadIdx.y + dy) * C + c0 + threadIdx.x];
    }
    __syncthreads();
    #pragma unroll
    for (int dy = 0; dy < 32; dy += 8) {
        out[(long)((c0 + threadIdx.y + dy) * stride + roff) * R + r0 + threadIdx.x] =
            __float2half_rn(t[threadIdx.x][threadIdx.y + dy]);
    }
}

// ---------------------------------------------------------------------------
// RMSNorm: fp32 in, half out
// ---------------------------------------------------------------------------
__global__ void rmsnorm_h(const float* __restrict__ x,
                          const float* __restrict__ g,
                          __half* __restrict__ out) {
    const int row = blockIdx.x;
    const int tid = threadIdx.x;
    const float* xr = x + (long)row * D_MODEL;
    float4 v = *reinterpret_cast<const float4*>(xr + tid * 4);
    float s = v.x * v.x + v.y * v.y + v.z * v.z + v.w * v.w;

    #pragma unroll
    for (int off = 16; off > 0; off >>= 1)
        s += __shfl_xor_sync(0xffffffffu, s, off);

    __shared__ float red[8];
    if ((tid & 31) == 0) red[tid >> 5] = s;
    __syncthreads();
    float total;
    {
        float t = (tid < 8) ? red[tid] : 0.f;
        #pragma unroll
        for (int off = 4; off > 0; off >>= 1)
            t += __shfl_xor_sync(0xffffffffu, t, off);
        __shared__ float bc;
        if (tid == 0) bc = t;
        __syncthreads();
        total = bc;
    }
    float inv = rsqrtf(total * (1.0f / D_MODEL) + 1e-6f);
    float4 gv = *reinterpret_cast<const float4*>(g + tid * 4);
    uint2 pk;
    pk.x = h2_u32(__floats2half2_rn(v.x * inv * gv.x, v.y * inv * gv.y));
    pk.y = h2_u32(__floats2half2_rn(v.z * inv * gv.z, v.w * inv * gv.w));
    *reinterpret_cast<uint2*>(out + (long)row * D_MODEL + tid * 4) = pk;
}

// ---------------------------------------------------------------------------
// RoPE table
// ---------------------------------------------------------------------------
__global__ void rope_tab_fill(float2* __restrict__ tab) {
    const int t = blockIdx.x;
    const int j = threadIdx.x;
    float inv = (float)exp(-(double)j / 32.0 * 9.210340371976184);
    float fr = (float)t * inv;
    tab[t * 32 + j] = make_float2(cosf(fr), sinf(fr));
}

// ---------------------------------------------------------------------------
// Launch
// ---------------------------------------------------------------------------
extern "C" void kernel_launch(void* const* d_in, const int* in_sizes, int n_in,
                              void* d_out, int out_size) {
    const float* x  = (const float*)d_in[0];
    const float* g1 = (const float*)d_in[1];
    const float* g2 = (const float*)d_in[2];
    const float* wq = (const float*)d_in[3];
    const float* wk = (const float*)d_in[4];
    const float* wv = (const float*)d_in[5];
    const float* wo = (const float*)d_in[6];
    const float* w1 = (const float*)d_in[7];
    const float* w2 = (const float*)d_in[8];
    const float* w3 = (const float*)d_in[9];
    float* out = (float*)d_out;

    __half *h, *qh, *kh, *vh, *ao, *h2, *a2;
    __half *wqkvT, *woT, *w12T, *w3T;
    float2* ropeT;
    cudaGetSymbolAddress((void**)&h,   g_h);
    cudaGetSymbolAddress((void**)&qh,  g_qh);
    cudaGetSymbolAddress((void**)&kh,  g_kh);
    cudaGetSymbolAddress((void**)&vh,  g_vh);
    cudaGetSymbolAddress((void**)&ao,  g_ao);
    cudaGetSymbolAddress((void**)&h2,  g_h2);
    cudaGetSymbolAddress((void**)&a2,  g_a2);
    cudaGetSymbolAddress((void**)&ropeT, g_rope);
    cudaGetSymbolAddress((void**)&wqkvT, g_wqkvT);
    cudaGetSymbolAddress((void**)&woT,  g_woT);
    cudaGetSymbolAddress((void**)&w12T, g_w12T);
    cudaGetSymbolAddress((void**)&w3T,  g_w3T);

    cudaFuncSetAttribute(hgemm, cudaFuncAttributeMaxDynamicSharedMemorySize,
                         GEMM_SMEM_BYTES);
    cudaFuncSetAttribute(attn_h, cudaFuncAttributeMaxDynamicSharedMemorySize,
                         ATTN_SMEM);

    dim3 tb(32, 8);
    transpose_h<<<dim3(D_MODEL / 32, D_MODEL / 32), tb>>>(wq, wqkvT, D_MODEL, D_MODEL, 1, 0);
    transpose_h<<<dim3((N_KV * HEAD_DIM) / 32, D_MODEL / 32), tb>>>(wk, wqkvT + 1024 * D_MODEL, D_MODEL, N_KV * HEAD_DIM, 1, 0);
    transpose_h<<<dim3((N_KV * HEAD_DIM) / 32, D_MODEL / 32), tb>>>(wv, wqkvT + 1536 * D_MODEL, D_MODEL, N_KV * HEAD_DIM, 1, 0);
    transpose_h<<<dim3(D_MODEL / 32, D_MODEL / 32), tb>>>(wo, woT, D_MODEL, D_MODEL, 1, 0);
    transpose_h<<<dim3(HIDDEN / 32, D_MODEL / 32), tb>>>(w1, w12T, D_MODEL, HIDDEN, 2, 0);
    transpose_h<<<dim3(HIDDEN / 32, D_MODEL / 32), tb>>>(w2, w12T, D_MODEL, HIDDEN, 2, 1);
    transpose_h<<<dim3(D_MODEL / 32, HIDDEN / 32), tb>>>(w3, w3T, HIDDEN, D_MODEL, 1, 0);
    rope_tab_fill<<<SEQ, 32>>>(ropeT);

    // 1. h = rmsnorm(x, g1)
    rmsnorm_h<<<BT, 256>>>(x, g1, h);

    // 2. fused qkv projection + RoPE + half conversion
    hgemm<<<dim3(QKV_N / 128, BT / 128), 128, GEMM_SMEM_BYTES>>>(
        h, wqkvT, nullptr, nullptr, BT, QKV_N, D_MODEL, EPI_ROPE,
        qh, kh, vh, ropeT);

    // 3. fp16 attention -> ao
    attn_h<<<dim3(SEQ / 128, BATCH * N_HEADS), 128, ATTN_SMEM>>>(qh, kh, vh, ao);

    // 4. out = ao @ wo + x
    hgemm<<<dim3(D_MODEL / 128, BT / 128), 128, GEMM_SMEM_BYTES>>>(
        ao, woT, x, out, BT, D_MODEL, D_MODEL, EPI_RES,
        nullptr, nullptr, nullptr, nullptr);

    // 5. h2 = rmsnorm(out, g2)
    rmsnorm_h<<<BT, 256>>>(out, g2, h2);

    // 6. fused FFN-up: a2 = silu(h2 @ w1) * (h2 @ w2)
    hgemm<<<dim3((2 * HIDDEN) / 128, BT / 128), 128, GEMM_SMEM_BYTES>>>(
        h2, w12T, nullptr, a2, BT, 2 * HIDDEN, D_MODEL, EPI_SWIGLU,
        nullptr, nullptr, nullptr, nullptr);

    // 7. out += a2 @ w3
    hgemm<<<dim3(D_MODEL / 128, BT / 128), 128, GEMM_SMEM_BYTES>>>(
        a2, w3T, out, out, BT, D_MODEL, HIDDEN, EPI_RES,
        nullptr, nullptr, nullptr, nullptr);
}

// round 16
// speedup vs baseline: 1.0459x; 1.0459x over previous
#include <cuda_runtime.h>
#include <cuda_fp16.h>
#include <math.h>
#include <stdint.h>

// ---------------------------------------------------------------------------
// Problem constants
// ---------------------------------------------------------------------------
#define D_MODEL   1024
#define N_HEADS   16
#define N_KV      8
#define HEAD_DIM  64
#define HIDDEN    4096
#define BATCH     4
#define SEQ       2048
#define BT        (BATCH * SEQ)
#define QKV_N     2048

// ---------------------------------------------------------------------------
// Scratch (device globals)
// ---------------------------------------------------------------------------
__device__ __half g_h  [BT * D_MODEL];
__device__ __half g_qh [BT * D_MODEL];
__device__ __half g_kh [BT * N_KV * HEAD_DIM];
__device__ __half g_vh [BT * N_KV * HEAD_DIM];
__device__ __half g_ao [BT * D_MODEL];
__device__ __half g_h2 [BT * D_MODEL];
__device__ __half g_a2 [BT * HIDDEN];
__device__ float2 g_rope[SEQ * 32];

__device__ __half g_wqkvT[QKV_N * D_MODEL];
__device__ __half g_woT [D_MODEL * D_MODEL];
__device__ __half g_w12T[2 * HIDDEN * D_MODEL];
__device__ __half g_w3T [D_MODEL * HIDDEN];

// ---------------------------------------------------------------------------
// Helpers
// ---------------------------------------------------------------------------
__device__ __forceinline__ void mma_f16(float* c, const uint32_t* a, const uint32_t* b) {
    asm volatile(
        "mma.sync.aligned.m16n8k16.row.col.f32.f16.f16.f32 "
        "{%0,%1,%2,%3}, {%4,%5,%6,%7}, {%8,%9}, {%0,%1,%2,%3};\n"
        : "+f"(c[0]), "+f"(c[1]), "+f"(c[2]), "+f"(c[3])
        : "r"(a[0]), "r"(a[1]), "r"(a[2]), "r"(a[3]), "r"(b[0]), "r"(b[1]));
}
__device__ __forceinline__ void ldm_x4(uint32_t* d, uint32_t saddr) {
    asm volatile(
        "ldmatrix.sync.aligned.m8n8.x4.shared.b16 {%0,%1,%2,%3}, [%4];"
        : "=r"(d[0]), "=r"(d[1]), "=r"(d[2]), "=r"(d[3]) : "r"(saddr));
}
__device__ __forceinline__ void ldm_x4_t(uint32_t* d, uint32_t saddr) {
    asm volatile(
        "ldmatrix.sync.aligned.m8n8.x4.trans.shared.b16 {%0,%1,%2,%3}, [%4];"
        : "=r"(d[0]), "=r"(d[1]), "=r"(d[2]), "=r"(d[3]) : "r"(saddr));
}
__device__ __forceinline__ uint32_t cvta_s(const void* p) {
    return (uint32_t)__cvta_generic_to_shared(p);
}
__device__ __forceinline__ void cp16(uint32_t dst, const void* src) {
    asm volatile(
        "{ .reg .u64 g; cvta.to.global.u64 g, %1; "
        "cp.async.cg.shared.global [%0], [g], 16; }"
        :: "r"(dst), "l"(src) : "memory");
}
#define CP_COMMIT() asm volatile("cp.async.commit_group;\n" ::: "memory")
#define CP_WAIT1()  asm volatile("cp.async.wait_group 1;\n" ::: "memory")
#define CP_WAIT0()  asm volatile("cp.async.wait_group 0;\n" ::: "memory")

__device__ __forceinline__ uint32_t h2_u32(__half2 h) {
    uint32_t u;
    *reinterpret_cast<__half2*>(&u) = h;
    return u;
}

#define EPI_RES    1
#define EPI_HALF   2
#define EPI_ROPE   4
#define EPI_SWIGLU 5

// ---------------------------------------------------------------------------
// fp16 tensor-core GEMM (exact R12: launch_bounds(128,2))
// ---------------------------------------------------------------------------
#define BKH   32
#define LDH   40
#define STG_H (128 * LDH)
#define GEMM_SMEM_BYTES (6 * STG_H * 2)

__global__ void __launch_bounds__(128, 2)
hgemm(const __half* __restrict__ A, const __half* __restrict__ Bt,
      const void* __restrict__ Rv, void* __restrict__ Cv,
      int M, int N, int K, int epi,
      __half* __restrict__ q_out, __half* __restrict__ k_out,
      __half* __restrict__ v_out, const float2* __restrict__ rope_tab) {
    extern __shared__ __half smh[];
    __half* Abuf[3] = { smh, smh + 2 * STG_H, smh + 4 * STG_H };
    __half* Bbuf[3] = { smh + STG_H, smh + 3 * STG_H, smh + 5 * STG_H };

    const int tid  = threadIdx.x;
    const int wid  = tid >> 5;
    const int lane = tid & 31;
    const int wm   = wid >> 1;
    const int wn   = wid & 1;
    const int gr   = lane >> 2;
    const int gc   = lane & 3;
    const int m0 = blockIdx.y << 7;
    const int n0 = blockIdx.x << 7;

    const int lr = tid >> 2;
    const int lc = (tid & 3) << 3;
    const __half* Ag = A  + (long)(m0 + lr) * K + lc;
    const __half* Bg = Bt + (long)(n0 + lr) * K + lc;

    uint32_t sA[3], sB[3], sAb[3], sBb[3];
    #pragma unroll
    for (int s = 0; s < 3; s++) {
        sAb[s] = cvta_s(Abuf[s]);
        sBb[s] = cvta_s(Bbuf[s]);
        sA[s] = cvta_s(&Abuf[s][lr * LDH + lc]);
        sB[s] = cvta_s(&Bbuf[s][lr * LDH + lc]);
    }
    const uint32_t rowstep = 32 * LDH * 2;

    const int l7  = lane & 7;
    const int sel = lane >> 3;
    const uint32_t aOff = (uint32_t)(((wm * 64 + l7 + (sel & 1) * 8) * LDH + (sel >> 1) * 8) * 2);
    const uint32_t bOff = (uint32_t)(((wn * 64 + l7 + (sel >> 1) * 8) * LDH + (sel & 1) * 8) * 2);

    const int NC = K / BKH;

    float acc[4][8][4];
    #pragma unroll
    for (int i = 0; i < 4; i++)
        #pragma unroll
        for (int j = 0; j < 8; j++)
            #pragma unroll
            for (int q = 0; q < 4; q++) acc[i][j][q] = 0.f;

    #pragma unroll
    for (int c0i = 0; c0i < 2; c0i++) {
        const long ko = (long)c0i * BKH;
        #pragma unroll
        for (int p = 0; p < 4; p++) {
            cp16(sA[c0i] + p * rowstep, Ag + (long)(p * 32) * K + ko);
            cp16(sB[c0i] + p * rowstep, Bg + (long)(p * 32) * K + ko);
        }
        CP_COMMIT();
    }

    for (int i = 0; i < NC; i++) {
        if (i < NC - 1) CP_WAIT1(); else CP_WAIT0();
        __syncthreads();

        if (i + 2 < NC) {
            const int s2 = (i + 2) % 3;
            const long ko = (long)(i + 2) * BKH;
            #pragma unroll
            for (int p = 0; p < 4; p++) {
                cp16(sA[s2] + p * rowstep, Ag + (long)(p * 32) * K + ko);
                cp16(sB[s2] + p * rowstep, Bg + (long)(p * 32) * K + ko);
            }
            CP_COMMIT();
        }

        const int cur = i % 3;
        const uint32_t aBase = sAb[cur] + aOff;
        const uint32_t bBase = sBb[cur] + bOff;

        #pragma unroll
        for (int ks = 0; ks < 2; ks++) {
            const uint32_t kb = (uint32_t)(ks * 16 * 2);
            uint32_t af[4][4], bf[8][2];
            #pragma unroll
            for (int mt = 0; mt < 4; mt++)
                ldm_x4(af[mt], aBase + (uint32_t)(mt * 16 * LDH * 2) + kb);
            #pragma unroll
            for (int np = 0; np < 4; np++) {
                uint32_t d[4];
                ldm_x4(d, bBase + (uint32_t)(np * 16 * LDH * 2) + kb);
                bf[np * 2][0]     = d[0]; bf[np * 2][1]     = d[1];
                bf[np * 2 + 1][0] = d[2]; bf[np * 2 + 1][1] = d[3];
            }
            #pragma unroll
            for (int mt = 0; mt < 4; mt++)
                #pragma unroll
                for (int nt = 0; nt < 8; nt++)
                    mma_f16(acc[mt][nt], af[mt], bf[nt]);
        }
    }
    __syncthreads();

    // ---------------- epilogues ----------------
    if (epi == EPI_ROPE) {
        const int head = (n0 + wn * 64) >> 6;
        #pragma unroll
        for (int mt = 0; mt < 4; mt++) {
            const int rowA = m0 + wm * 64 + mt * 16 + gr;
            const int rowB = rowA + 8;
            const int tA = rowA & (SEQ - 1);
            const int tB = rowB & (SEQ - 1);
            if (head < 24) {
                __half* dstA;
                long stride;
                if (head < 16) {
                    dstA = q_out + (long)rowA * D_MODEL + head * HEAD_DIM;
                    stride = D_MODEL;
                } else {
                    dstA = k_out + (long)rowA * (N_KV * HEAD_DIM) + (head - 16) * HEAD_DIM;
                    stride = N_KV * HEAD_DIM;
                }
                __half* dstB = dstA + 8 * stride;
                #pragma unroll
                for (int nt = 0; nt < 4; nt++) {
                    const int j0 = nt * 8 + gc * 2;
                    const float2 cA0 = rope_tab[tA * 32 + j0];
                    const float2 cA1 = rope_tab[tA * 32 + j0 + 1];
                    const float2 cB0 = rope_tab[tB * 32 + j0];
                    const float2 cB1 = rope_tab[tB * 32 + j0 + 1];
                    const float x1a0 = acc[mt][nt][0],     x1a1 = acc[mt][nt][1];
                    const float x1b0 = acc[mt][nt][2],     x1b1 = acc[mt][nt][3];
                    const float x2a0 = acc[mt][nt + 4][0], x2a1 = acc[mt][nt + 4][1];
                    const float x2b0 = acc[mt][nt + 4][2], x2b1 = acc[mt][nt + 4][3];
                    *reinterpret_cast<__half2*>(dstA + j0) =
                        __floats2half2_rn(x1a0 * cA0.x - x2a0 * cA0.y,
                                          x1a1 * cA1.x - x2a1 * cA1.y);
                    *reinterpret_cast<__half2*>(dstA + j0 + 32) =
                        __floats2half2_rn(x2a0 * cA0.x + x1a0 * cA0.y,
                                          x2a1 * cA1.x + x1a1 * cA1.y);
                    *reinterpret_cast<__half2*>(dstB + j0) =
                        __floats2half2_rn(x1b0 * cB0.x - x2b0 * cB0.y,
                                          x1b1 * cB1.x - x2b1 * cB1.y);
                    *reinterpret_cast<__half2*>(dstB + j0 + 32) =
                        __floats2half2_rn(x2b0 * cB0.x + x1b0 * cB0.y,
                                          x2b1 * cB1.x + x1b1 * cB1.y);
                }
            } else {
                __half* dstA = v_out + (long)rowA * (N_KV * HEAD_DIM) + (head - 24) * HEAD_DIM;
                __half* dstB = dstA + 8 * (N_KV * HEAD_DIM);
                #pragma unroll
                for (int nt = 0; nt < 8; nt++) {
                    const int c = nt * 8 + gc * 2;
                    *reinterpret_cast<__half2*>(dstA + c) =
                        __floats2half2_rn(acc[mt][nt][0], acc[mt][nt][1]);
                    *reinterpret_cast<__half2*>(dstB + c) =
                        __floats2half2_rn(acc[mt][nt][2], acc[mt][nt][3]);
                }
            }
        }
        return;
    }

    if (epi == EPI_SWIGLU) {
        __half* C = (__half*)Cv;
        const int NH = N >> 1;
        #pragma unroll
        for (int mt = 0; mt < 4; mt++) {
            #pragma unroll
            for (int nt = 0; nt < 8; nt++) {
                const int row = m0 + wm * 64 + mt * 16 + gr;
                const int jcol = ((n0 + wn * 64 + nt * 8) >> 1) + gc;
                const float aA = acc[mt][nt][0], bA = acc[mt][nt][1];
                const float aB = acc[mt][nt][2], bB = acc[mt][nt][3];
                C[(long)row * NH + jcol] =
                    __float2half_rn(aA / (1.0f + __expf(-aA)) * bA);
                C[(long)(row + 8) * NH + jcol] =
                    __float2half_rn(aB / (1.0f + __expf(-aB)) * bB);
            }
        }
        return;
    }

    #pragma unroll
    for (int mt = 0; mt < 4; mt++) {
        #pragma unroll
        for (int nt = 0; nt < 8; nt++) {
            const int row = m0 + wm * 64 + mt * 16 + gr;
            const int col = n0 + wn * 64 + nt * 8 + gc * 2;
            const long offA = (long)row * N + col;
            const long offB = (long)(row + 8) * N + col;
            float2 lo = make_float2(acc[mt][nt][0], acc[mt][nt][1]);
            float2 hi = make_float2(acc[mt][nt][2], acc[mt][nt][3]);
            if (epi == EPI_RES) {
                const float* R = (const float*)Rv;
                float2 r0 = *reinterpret_cast<const float2*>(R + offA);
                float2 r1 = *reinterpret_cast<const float2*>(R + offB);
                lo.x += r0.x; lo.y += r0.y;
                hi.x += r1.x; hi.y += r1.y;
                *reinterpret_cast<float2*>((float*)Cv + offA) = lo;
                *reinterpret_cast<float2*>((float*)Cv + offB) = hi;
            } else {  // EPI_HALF
                *reinterpret_cast<__half2*>((__half*)Cv + offA) = __floats2half2_rn(lo.x, lo.y);
                *reinterpret_cast<__half2*>((__half*)Cv + offB) = __floats2half2_rn(hi.x, hi.y);
            }
        }
    }
}

// ---------------------------------------------------------------------------
// fp16 flash attention, causal GQA (exact R12: 128 thr, 4 warps x 32 rows,
// natural launch order)
// ---------------------------------------------------------------------------
#define QS_LDH 72
#define KS_LDH 72
#define VS_LDH 72
#define ATTN_SMEM ((128 * QS_LDH + 2 * 64 * KS_LDH + 2 * 64 * VS_LDH) * 2)

__global__ void __launch_bounds__(128, 2)
attn_h(const __half* __restrict__ qh, const __half* __restrict__ kh,
       const __half* __restrict__ vh, __half* __restrict__ o) {
    extern __shared__ __half smh[];
    __half* Qs = smh;
    __half* Kb[2] = { smh + 128 * QS_LDH, smh + 128 * QS_LDH + 64 * KS_LDH };
    __half* Vb[2] = { Kb[1] + 64 * KS_LDH, Kb[1] + 64 * KS_LDH + 64 * VS_LDH };

    const int tid  = threadIdx.x;
    const int warp = tid >> 5;
    const int lane = tid & 31;
    const int gr = lane >> 2;
    const int gc = lane & 3;
    const int wr = warp << 5;

    const int t0  = blockIdx.x << 7;
    const int bh  = blockIdx.y;
    const int b   = bh >> 4;
    const int hq  = bh & 15;
    const int kvh = hq >> 1;

    const uint32_t qsb = cvta_s(Qs);
    uint32_t ksb[2] = { cvta_s(Kb[0]), cvta_s(Kb[1]) };
    uint32_t vsb[2] = { cvta_s(Vb[0]), cvta_s(Vb[1]) };

    const int l7  = lane & 7;
    const int sel = lane >> 3;
    const uint32_t aQoff = (uint32_t)(((wr + l7 + (sel & 1) * 8) * QS_LDH + (sel >> 1) * 8) * 2);
    const uint32_t bKoff = (uint32_t)(((l7 + (sel >> 1) * 8) * KS_LDH + (sel & 1) * 8) * 2);
    const uint32_t vToff = (uint32_t)((((sel & 1) * 8 + l7) * VS_LDH + (sel >> 1) * 8) * 2);

    const int ldr = tid >> 3;
    const int ldc = (tid & 7) << 3;

    {
        #pragma unroll
        for (int p = 0; p < 8; p++) {
            const int row = ldr + p * 16;
            cp16(qsb + (uint32_t)((row * QS_LDH + ldc) * 2),
                 qh + (long)(b * SEQ + t0 + row) * D_MODEL + hq * HEAD_DIM + ldc);
        }
    }
    {
        #pragma unroll
        for (int p = 0; p < 4; p++) {
            const int row = ldr + p * 16;
            const long base = (long)(b * SEQ + row) * (N_KV * HEAD_DIM) + kvh * HEAD_DIM + ldc;
            cp16(ksb[0] + (uint32_t)((row * KS_LDH + ldc) * 2), kh + base);
            cp16(vsb[0] + (uint32_t)((row * VS_LDH + ldc) * 2), vh + base);
        }
        CP_COMMIT();
    }

    float ofrag[2][8][4];
    #pragma unroll
    for (int mt = 0; mt < 2; mt++)
        #pragma unroll
        for (int nt = 0; nt < 8; nt++)
            #pragma unroll
            for (int r = 0; r < 4; r++) ofrag[mt][nt][r] = 0.f;

    float mrow[2][2] = {{-1e30f, -1e30f}, {-1e30f, -1e30f}};
    float lrow[2][2] = {{0.f, 0.f}, {0.f, 0.f}};
    const float SC = 0.125f;

    const int ntiles = (t0 >> 6) + 2;
    for (int it = 0; it < ntiles; it++) {
        const int s0 = it << 6;
        const int cur = it & 1;

        if (it + 1 < ntiles) {
            const int nxt = cur ^ 1;
            const long roff = (long)((it + 1) << 6) * (N_KV * HEAD_DIM);
            #pragma unroll
            for (int p = 0; p < 4; p++) {
                const int row = ldr + p * 16;
                const long base = (long)(b * SEQ + row) * (N_KV * HEAD_DIM) + kvh * HEAD_DIM + ldc + roff;
                cp16(ksb[nxt] + (uint32_t)((row * KS_LDH + ldc) * 2), kh + base);
                cp16(vsb[nxt] + (uint32_t)((row * VS_LDH + ldc) * 2), vh + base);
            }
            CP_COMMIT();
            CP_WAIT1();
        } else {
            CP_WAIT0();
        }
        __syncthreads();

        float sfrag[2][8][4];
        #pragma unroll
        for (int mt = 0; mt < 2; mt++)
            #pragma unroll
            for (int nt = 0; nt < 8; nt++)
                #pragma unroll
                for (int r = 0; r < 4; r++) sfrag[mt][nt][r] = 0.f;

        #pragma unroll
        for (int ks = 0; ks < 4; ks++) {
            const uint32_t kb = (uint32_t)(ks * 16 * 2);
            uint32_t aq[2][4], bk[8][2];
            #pragma unroll
            for (int mt = 0; mt < 2; mt++)
                ldm_x4(aq[mt], qsb + aQoff + (uint32_t)(mt * 16 * QS_LDH * 2) + kb);
            #pragma unroll
            for (int np = 0; np < 4; np++) {
                uint32_t d[4];
                ldm_x4(d, ksb[cur] + bKoff + (uint32_t)(np * 16 * KS_LDH * 2) + kb);
                bk[np * 2][0]     = d[0]; bk[np * 2][1]     = d[1];
                bk[np * 2 + 1][0] = d[2]; bk[np * 2 + 1][1] = d[3];
            }
            #pragma unroll
            for (int mt = 0; mt < 2; mt++)
                #pragma unroll
                for (int nt = 0; nt < 8; nt++)
                    mma_f16(sfrag[mt][nt], aq[mt], bk[nt]);
        }

        if (it >= ntiles - 2) {
            #pragma unroll
            for (int mt = 0; mt < 2; mt++) {
                const int rA = t0 + wr + mt * 16 + gr;
                const int rB = rA + 8;
                #pragma unroll
                for (int nt = 0; nt < 8; nt++) {
                    const int cb = s0 + nt * 8 + 2 * gc;
                    if (cb     > rA) sfrag[mt][nt][0] = -1e30f;
                    if (cb + 1 > rA) sfrag[mt][nt][1] = -1e30f;
                    if (cb     > rB) sfrag[mt][nt][2] = -1e30f;
                    if (cb + 1 > rB) sfrag[mt][nt][3] = -1e30f;
                }
            }
        }

        #pragma unroll
        for (int mt = 0; mt < 2; mt++) {
            float r0 = -1e30f, r1 = -1e30f;
            #pragma unroll
            for (int nt = 0; nt < 8; nt++) {
                r0 = fmaxf(r0, fmaxf(sfrag[mt][nt][0], sfrag[mt][nt][1]));
                r1 = fmaxf(r1, fmaxf(sfrag[mt][nt][2], sfrag[mt][nt][3]));
            }
            r0 = fmaxf(r0, __shfl_xor_sync(0xffffffffu, r0, 1));
            r0 = fmaxf(r0, __shfl_xor_sync(0xffffffffu, r0, 2));
            r1 = fmaxf(r1, __shfl_xor_sync(0xffffffffu, r1, 1));
            r1 = fmaxf(r1, __shfl_xor_sync(0xffffffffu, r1, 2));

            const float mn0 = fmaxf(mrow[mt][0], r0);
            const float mn1 = fmaxf(mrow[mt][1], r1);
            const float c0 = __expf((mrow[mt][0] - mn0) * SC);
            const float c1 = __expf((mrow[mt][1] - mn1) * SC);
            lrow[mt][0] *= c0;
            lrow[mt][1] *= c1;
            #pragma unroll
            for (int nt = 0; nt < 8; nt++) {
                ofrag[mt][nt][0] *= c0; ofrag[mt][nt][1] *= c0;
                ofrag[mt][nt][2] *= c1; ofrag[mt][nt][3] *= c1;
            }
            float s0s = 0.f, s1s = 0.f;
            #pragma unroll
            for (int nt = 0; nt < 8; nt++) {
                sfrag[mt][nt][0] = __expf((sfrag[mt][nt][0] - mn0) * SC);
                sfrag[mt][nt][1] = __expf((sfrag[mt][nt][1] - mn0) * SC);
                sfrag[mt][nt][2] = __expf((sfrag[mt][nt][2] - mn1) * SC);
                sfrag[mt][nt][3] = __expf((sfrag[mt][nt][3] - mn1) * SC);
                s0s += sfrag[mt][nt][0] + sfrag[mt][nt][1];
                s1s += sfrag[mt][nt][2] + sfrag[mt][nt][3];
            }
            s0s += __shfl_xor_sync(0xffffffffu, s0s, 1);
            s0s += __shfl_xor_sync(0xffffffffu, s0s, 2);
            s1s += __shfl_xor_sync(0xffffffffu, s1s, 1);
            s1s += __shfl_xor_sync(0xffffffffu, s1s, 2);
            lrow[mt][0] += s0s;
            lrow[mt][1] += s1s;
            mrow[mt][0] = mn0;
            mrow[mt][1] = mn1;
        }

        #pragma unroll
        for (int ks = 0; ks < 4; ks++) {
            uint32_t ap[2][4];
            #pragma unroll
            for (int mt = 0; mt < 2; mt++) {
                ap[mt][0] = h2_u32(__floats2half2_rn(sfrag[mt][2 * ks][0],     sfrag[mt][2 * ks][1]));
                ap[mt][1] = h2_u32(__floats2half2_rn(sfrag[mt][2 * ks][2],     sfrag[mt][2 * ks][3]));
                ap[mt][2] = h2_u32(__floats2half2_rn(sfrag[mt][2 * ks + 1][0], sfrag[mt][2 * ks + 1][1]));
                ap[mt][3] = h2_u32(__floats2half2_rn(sfrag[mt][2 * ks + 1][2], sfrag[mt][2 * ks + 1][3]));
            }
            uint32_t bv[8][2];
            #pragma unroll
            for (int np = 0; np < 4; np++) {
                uint32_t d[4];
                ldm_x4_t(d, vsb[cur] + vToff +
                            (uint32_t)((ks * 16 * VS_LDH + np * 16) * 2));
                bv[np * 2][0]     = d[0]; bv[np * 2][1]     = d[1];
                bv[np * 2 + 1][0] = d[2]; bv[np * 2 + 1][1] = d[3];
            }
            #pragma unroll
            for (int mt = 0; mt < 2; mt++)
                #pragma unroll
                for (int nt = 0; nt < 8; nt++)
                    mma_f16(ofrag[mt][nt], ap[mt], bv[nt]);
        }
        __syncthreads();
    }

    #pragma unroll
    for (int mt = 0; mt < 2; mt++) {
        const int rowA = t0 + wr + mt * 16 + gr;
        const int rowB = rowA + 8;
        const float il0 = 1.0f / lrow[mt][0];
        const float il1 = 1.0f / lrow[mt][1];
        #pragma unroll
        for (int nt = 0; nt < 8; nt++) {
            const int col = hq * HEAD_DIM + nt * 8 + 2 * gc;
            *reinterpret_cast<__half2*>(o + (long)(b * SEQ + rowA) * D_MODEL + col) =
                __floats2half2_rn(ofrag[mt][nt][0] * il0, ofrag[mt][nt][1] * il0);
            *reinterpret_cast<__half2*>(o + (long)(b * SEQ + rowB) * D_MODEL + col) =
                __floats2half2_rn(ofrag[mt][nt][2] * il1, ofrag[mt][nt][3] * il1);
        }
    }
}

// ---------------------------------------------------------------------------
// Fused prep: 7 weight transposes (fp32->half, 32x32 tiles) + rope table, ONE
// launch (isolated test of R13's fusion, without LPT).
// ---------------------------------------------------------------------------
#define SEG_WQ   0
#define SEG_WK   1024
#define SEG_WV   1536
#define SEG_WO   2048
#define SEG_W1   3072
#define SEG_W2   7168
#define SEG_W3   11264
#define SEG_ROPE 15360
#define PREP_BLOCKS (SEG_ROPE + 8)

__device__ __forceinline__ void tr_tile(const float* __restrict__ in,
                                        __half* __restrict__ out,
                                        int R, int C, int stride, int roff,
                                        int cx, int ry) {
    __shared__ float t[32][33];
    const int c0 = cx << 5, r0 = ry << 5;
    #pragma unroll
    for (int dy = 0; dy < 32; dy += 8) {
        t[threadIdx.y + dy][threadIdx.x] =
            in[(long)(r0 + threadIdx.y + dy) * C + c0 + threadIdx.x];
    }
    __syncthreads();
    #pragma unroll
    for (int dy = 0; dy < 32; dy += 8) {
        out[(long)((c0 + threadIdx.y + dy) * stride + roff) * R + r0 + threadIdx.x] =
            __float2half_rn(t[threadIdx.x][threadIdx.y + dy]);
    }
}

__global__ void prep_kernel(const float* __restrict__ wq, const float* __restrict__ wk,
                            const float* __restrict__ wv, const float* __restrict__ wo,
                            const float* __restrict__ w1, const float* __restrict__ w2,
                            const float* __restrict__ w3,
                            __half* __restrict__ wqkvT, __half* __restrict__ woT,
                            __half* __restrict__ w12T, __half* __restrict__ w3T,
                            float2* __restrict__ ropeT) {
    const int bid = blockIdx.x;
    if (bid < SEG_WK) {
        const int u = bid - SEG_WQ;
        tr_tile(wq, wqkvT, D_MODEL, D_MODEL, 1, 0, u & 31, u >> 5);
    } else if (bid < SEG_WV) {
        const int u = bid - SEG_WK;
        tr_tile(wk, wqkvT + 1024 * D_MODEL, D_MODEL, 512, 1, 0, u & 15, u >> 4);
    } else if (bid < SEG_WO) {
        const int u = bid - SEG_WV;
        tr_tile(wv, wqkvT + 1536 * D_MODEL, D_MODEL, 512, 1, 0, u & 15, u >> 4);
    } else if (bid < SEG_W1) {
        const int u = bid - SEG_WO;
        tr_tile(wo, woT, D_MODEL, D_MODEL, 1, 0, u & 31, u >> 5);
    } else if (bid < SEG_W2) {
        const int u = bid - SEG_W1;
        tr_tile(w1, w12T, D_MODEL, HIDDEN, 2, 0, u & 127, u >> 7);
    } else if (bid < SEG_W3) {
        const int u = bid - SEG_W2;
        tr_tile(w2, w12T, D_MODEL, HIDDEN, 2, 1, u & 127, u >> 7);
    } else if (bid < SEG_ROPE) {
        const int u = bid - SEG_W3;
        tr_tile(w3, w3T, HIDDEN, D_MODEL, 1, 0, u & 31, u >> 5);
    } else {
        const int u = bid - SEG_ROPE;
        const int t = u * 256 + threadIdx.y * 32 + threadIdx.x;
        const int base = t * 32;
        #pragma unroll
        for (int j = 0; j < 32; j++) {
            float inv = (float)exp(-(double)j / 32.0 * 9.210340371976184);
            float fr = (float)t * inv;
            ropeT[base + j] = make_float2(cosf(fr), sinf(fr));
        }
    }
}

// ---------------------------------------------------------------------------
// RMSNorm: fp32 in, half out
// ---------------------------------------------------------------------------
__global__ void rmsnorm_h(const float* __restrict__ x,
                          const float* __restrict__ g,
                          __half* __restrict__ out) {
    const int row = blockIdx.x;
    const int tid = threadIdx.x;
    const float* xr = x + (long)row * D_MODEL;
    float4 v = *reinterpret_cast<const float4*>(xr + tid * 4);
    float s = v.x * v.x + v.y * v.y + v.z * v.z + v.w * v.w;

    #pragma unroll
    for (int off = 16; off > 0; off >>= 1)
        s += __shfl_xor_sync(0xffffffffu, s, off);

    __shared__ float red[8];
    if ((tid & 31) == 0) red[tid >> 5] = s;
    __syncthreads();
    float total;
    {
        float t = (tid < 8) ? red[tid] : 0.f;
        #pragma unroll
        for (int off = 4; off > 0; off >>= 1)
            t += __shfl_xor_sync(0xffffffffu, t, off);
        __shared__ float bc;
        if (tid == 0) bc = t;
        __syncthreads();
        total = bc;
    }
    float inv = rsqrtf(total * (1.0f / D_MODEL) + 1e-6f);
    float4 gv = *reinterpret_cast<const float4*>(g + tid * 4);
    uint2 pk;
    pk.x = h2_u32(__floats2half2_rn(v.x * inv * gv.x, v.y * inv * gv.y));
    pk.y = h2_u32(__floats2half2_rn(v.z * inv * gv.z, v.w * inv * gv.w));
    *reinterpret_cast<uint2*>(out + (long)row * D_MODEL + tid * 4) = pk;
}

// ---------------------------------------------------------------------------
// Launch
// ---------------------------------------------------------------------------
extern "C" void kernel_launch(void* const* d_in, const int* in_sizes, int n_in,
                              void* d_out, int out_size) {
    const float* x  = (const float*)d_in[0];
    const float* g1 = (const float*)d_in[1];
    const float* g2 = (const float*)d_in[2];
    const float* wq = (const float*)d_in[3];
    const float* wk = (const float*)d_in[4];
    const float* wv = (const float*)d_in[5];
    const float* wo = (const float*)d_in[6];
    const float* w1 = (const float*)d_in[7];
    const float* w2 = (const float*)d_in[8];
    const float* w3 = (const float*)d_in[9];
    float* out = (float*)d_out;

    __half *h, *qh, *kh, *vh, *ao, *h2, *a2;
    __half *wqkvT, *woT, *w12T, *w3T;
    float2* ropeT;
    cudaGetSymbolAddress((void**)&h,   g_h);
    cudaGetSymbolAddress((void**)&qh,  g_qh);
    cudaGetSymbolAddress((void**)&kh,  g_kh);
    cudaGetSymbolAddress((void**)&vh,  g_vh);
    cudaGetSymbolAddress((void**)&ao,  g_ao);
    cudaGetSymbolAddress((void**)&h2,  g_h2);
    cudaGetSymbolAddress((void**)&a2,  g_a2);
    cudaGetSymbolAddress((void**)&ropeT, g_rope);
    cudaGetSymbolAddress((void**)&wqkvT, g_wqkvT);
    cudaGetSymbolAddress((void**)&woT,  g_woT);
    cudaGetSymbolAddress((void**)&w12T, g_w12T);
    cudaGetSymbolAddress((void**)&w3T,  g_w3T);

    cudaFuncSetAttribute(hgemm, cudaFuncAttributeMaxDynamicSharedMemorySize,
                         GEMM_SMEM_BYTES);
    cudaFuncSetAttribute(attn_h, cudaFuncAttributeMaxDynamicSharedMemorySize,
                         ATTN_SMEM);

    // 0. all weight transposes + rope table, one launch
    prep_kernel<<<PREP_BLOCKS, dim3(32, 8)>>>(wq, wk, wv, wo, w1, w2, w3,
                                              wqkvT, woT, w12T, w3T, ropeT);

    // 1. h = rmsnorm(x, g1)
    rmsnorm_h<<<BT, 256>>>(x, g1, h);

    // 2. fused qkv projection + RoPE + half conversion
    hgemm<<<dim3(QKV_N / 128, BT / 128), 128, GEMM_SMEM_BYTES>>>(
        h, wqkvT, nullptr, nullptr, BT, QKV_N, D_MODEL, EPI_ROPE,
        qh, kh, vh, ropeT);

    // 3. fp16 attention -> ao
    attn_h<<<dim3(SEQ / 128, BATCH * N_HEADS), 128, ATTN_SMEM>>>(qh, kh, vh, ao);

    // 4. out = ao @ wo + x
    hgemm<<<dim3(D_MODEL / 128, BT / 128), 128, GEMM_SMEM_BYTES>>>(
        ao, woT, x, out, BT, D_MODEL, D_MODEL, EPI_RES,
        nullptr, nullptr, nullptr, nullptr);

    // 5. h2 = rmsnorm(out, g2)
    rmsnorm_h<<<BT, 256>>>(out, g2, h2);

    // 6. fused FFN-up: a2 = silu(h2 @ w1) * (h2 @ w2)
    hgemm<<<dim3((2 * HIDDEN) / 128, BT / 128), 128, GEMM_SMEM_BYTES>>>(
        h2, w12T, nullptr, a2, BT, 2 * HIDDEN, D_MODEL, EPI_SWIGLU,
        nullptr, nullptr, nullptr, nullptr);

    // 7. out += a2 @ w3
    hgemm<<<dim3(D_MODEL / 128, BT / 128), 128, GEMM_SMEM_BYTES>>>(
        a2, w3T, out, out, BT, D_MODEL, HIDDEN, EPI_RES,
        nullptr, nullptr, nullptr, nullptr);
}

// round 17
// speedup vs baseline: 1.0919x; 1.0440x over previous
#include <cuda_runtime.h>
#include <cuda_fp16.h>
#include <math.h>
#include <stdint.h>

// ---------------------------------------------------------------------------
// Problem constants
// ---------------------------------------------------------------------------
#define D_MODEL   1024
#define N_HEADS   16
#define N_KV      8
#define HEAD_DIM  64
#define HIDDEN    4096
#define BATCH     4
#define SEQ       2048
#define BT        (BATCH * SEQ)
#define QKV_N     2048

// ---------------------------------------------------------------------------
// Scratch (device globals)
// ---------------------------------------------------------------------------
__device__ __half g_h  [BT * D_MODEL];
__device__ __half g_qh [BT * D_MODEL];
__device__ __half g_kh [BT * N_KV * HEAD_DIM];
__device__ __half g_vh [BT * N_KV * HEAD_DIM];
__device__ __half g_ao [BT * D_MODEL];
__device__ __half g_h2 [BT * D_MODEL];
__device__ __half g_a2 [BT * HIDDEN];
__device__ float2 g_rope[SEQ * 32];

__device__ __half g_wqkvT[QKV_N * D_MODEL];
__device__ __half g_woT [D_MODEL * D_MODEL];
__device__ __half g_w12T[2 * HIDDEN * D_MODEL];
__device__ __half g_w3T [D_MODEL * HIDDEN];

// ---------------------------------------------------------------------------
// Helpers
// ---------------------------------------------------------------------------
__device__ __forceinline__ void mma_f16(float* c, const uint32_t* a, const uint32_t* b) {
    asm volatile(
        "mma.sync.aligned.m16n8k16.row.col.f32.f16.f16.f32 "
        "{%0,%1,%2,%3}, {%4,%5,%6,%7}, {%8,%9}, {%0,%1,%2,%3};\n"
        : "+f"(c[0]), "+f"(c[1]), "+f"(c[2]), "+f"(c[3])
        : "r"(a[0]), "r"(a[1]), "r"(a[2]), "r"(a[3]), "r"(b[0]), "r"(b[1]));
}
__device__ __forceinline__ void ldm_x4(uint32_t* d, uint32_t saddr) {
    asm volatile(
        "ldmatrix.sync.aligned.m8n8.x4.shared.b16 {%0,%1,%2,%3}, [%4];"
        : "=r"(d[0]), "=r"(d[1]), "=r"(d[2]), "=r"(d[3]) : "r"(saddr));
}
__device__ __forceinline__ void ldm_x4_t(uint32_t* d, uint32_t saddr) {
    asm volatile(
        "ldmatrix.sync.aligned.m8n8.x4.trans.shared.b16 {%0,%1,%2,%3}, [%4];"
        : "=r"(d[0]), "=r"(d[1]), "=r"(d[2]), "=r"(d[3]) : "r"(saddr));
}
__device__ __forceinline__ uint32_t cvta_s(const void* p) {
    return (uint32_t)__cvta_generic_to_shared(p);
}
__device__ __forceinline__ void cp16(uint32_t dst, const void* src) {
    asm volatile(
        "{ .reg .u64 g; cvta.to.global.u64 g, %1; "
        "cp.async.cg.shared.global [%0], [g], 16; }"
        :: "r"(dst), "l"(src) : "memory");
}
#define CP_COMMIT() asm volatile("cp.async.commit_group;\n" ::: "memory")
#define CP_WAIT1()  asm volatile("cp.async.wait_group 1;\n" ::: "memory")
#define CP_WAIT0()  asm volatile("cp.async.wait_group 0;\n" ::: "memory")

__device__ __forceinline__ uint32_t h2_u32(__half2 h) {
    uint32_t u;
    *reinterpret_cast<__half2*>(&u) = h;
    return u;
}

#define EPI_RES    1
#define EPI_HALF   2
#define EPI_ROPE   4
#define EPI_SWIGLU 5

// ---------------------------------------------------------------------------
// fp16 tensor-core GEMM (exact R12: launch_bounds(128,2))
// ---------------------------------------------------------------------------
#define BKH   32
#define LDH   40
#define STG_H (128 * LDH)
#define GEMM_SMEM_BYTES (6 * STG_H * 2)

__global__ void __launch_bounds__(128, 2)
hgemm(const __half* __restrict__ A, const __half* __restrict__ Bt,
      const void* __restrict__ Rv, void* __restrict__ Cv,
      int M, int N, int K, int epi,
      __half* __restrict__ q_out, __half* __restrict__ k_out,
      __half* __restrict__ v_out, const float2* __restrict__ rope_tab) {
    extern __shared__ __half smh[];
    __half* Abuf[3] = { smh, smh + 2 * STG_H, smh + 4 * STG_H };
    __half* Bbuf[3] = { smh + STG_H, smh + 3 * STG_H, smh + 5 * STG_H };

    const int tid  = threadIdx.x;
    const int wid  = tid >> 5;
    const int lane = tid & 31;
    const int wm   = wid >> 1;
    const int wn   = wid & 1;
    const int gr   = lane >> 2;
    const int gc   = lane & 3;
    const int m0 = blockIdx.y << 7;
    const int n0 = blockIdx.x << 7;

    const int lr = tid >> 2;
    const int lc = (tid & 3) << 3;
    const __half* Ag = A  + (long)(m0 + lr) * K + lc;
    const __half* Bg = Bt + (long)(n0 + lr) * K + lc;

    uint32_t sA[3], sB[3], sAb[3], sBb[3];
    #pragma unroll
    for (int s = 0; s < 3; s++) {
        sAb[s] = cvta_s(Abuf[s]);
        sBb[s] = cvta_s(Bbuf[s]);
        sA[s] = cvta_s(&Abuf[s][lr * LDH + lc]);
        sB[s] = cvta_s(&Bbuf[s][lr * LDH + lc]);
    }
    const uint32_t rowstep = 32 * LDH * 2;

    const int l7  = lane & 7;
    const int sel = lane >> 3;
    const uint32_t aOff = (uint32_t)(((wm * 64 + l7 + (sel & 1) * 8) * LDH + (sel >> 1) * 8) * 2);
    const uint32_t bOff = (uint32_t)(((wn * 64 + l7 + (sel >> 1) * 8) * LDH + (sel & 1) * 8) * 2);

    const int NC = K / BKH;

    float acc[4][8][4];
    #pragma unroll
    for (int i = 0; i < 4; i++)
        #pragma unroll
        for (int j = 0; j < 8; j++)
            #pragma unroll
            for (int q = 0; q < 4; q++) acc[i][j][q] = 0.f;

    #pragma unroll
    for (int c0i = 0; c0i < 2; c0i++) {
        const long ko = (long)c0i * BKH;
        #pragma unroll
        for (int p = 0; p < 4; p++) {
            cp16(sA[c0i] + p * rowstep, Ag + (long)(p * 32) * K + ko);
            cp16(sB[c0i] + p * rowstep, Bg + (long)(p * 32) * K + ko);
        }
        CP_COMMIT();
    }

    for (int i = 0; i < NC; i++) {
        if (i < NC - 1) CP_WAIT1(); else CP_WAIT0();
        __syncthreads();

        if (i + 2 < NC) {
            const int s2 = (i + 2) % 3;
            const long ko = (long)(i + 2) * BKH;
            #pragma unroll
            for (int p = 0; p < 4; p++) {
                cp16(sA[s2] + p * rowstep, Ag + (long)(p * 32) * K + ko);
                cp16(sB[s2] + p * rowstep, Bg + (long)(p * 32) * K + ko);
            }
            CP_COMMIT();
        }

        const int cur = i % 3;
        const uint32_t aBase = sAb[cur] + aOff;
        const uint32_t bBase = sBb[cur] + bOff;

        #pragma unroll
        for (int ks = 0; ks < 2; ks++) {
            const uint32_t kb = (uint32_t)(ks * 16 * 2);
            uint32_t af[4][4], bf[8][2];
            #pragma unroll
            for (int mt = 0; mt < 4; mt++)
                ldm_x4(af[mt], aBase + (uint32_t)(mt * 16 * LDH * 2) + kb);
            #pragma unroll
            for (int np = 0; np < 4; np++) {
                uint32_t d[4];
                ldm_x4(d, bBase + (uint32_t)(np * 16 * LDH * 2) + kb);
                bf[np * 2][0]     = d[0]; bf[np * 2][1]     = d[1];
                bf[np * 2 + 1][0] = d[2]; bf[np * 2 + 1][1] = d[3];
            }
            #pragma unroll
            for (int mt = 0; mt < 4; mt++)
                #pragma unroll
                for (int nt = 0; nt < 8; nt++)
                    mma_f16(acc[mt][nt], af[mt], bf[nt]);
        }
    }
    __syncthreads();

    // ---------------- epilogues ----------------
    if (epi == EPI_ROPE) {
        const int head = (n0 + wn * 64) >> 6;
        #pragma unroll
        for (int mt = 0; mt < 4; mt++) {
            const int rowA = m0 + wm * 64 + mt * 16 + gr;
            const int rowB = rowA + 8;
            const int tA = rowA & (SEQ - 1);
            const int tB = rowB & (SEQ - 1);
            if (head < 24) {
                __half* dstA;
                long stride;
                if (head < 16) {
                    dstA = q_out + (long)rowA * D_MODEL + head * HEAD_DIM;
                    stride = D_MODEL;
                } else {
                    dstA = k_out + (long)rowA * (N_KV * HEAD_DIM) + (head - 16) * HEAD_DIM;
                    stride = N_KV * HEAD_DIM;
                }
                __half* dstB = dstA + 8 * stride;
                #pragma unroll
                for (int nt = 0; nt < 4; nt++) {
                    const int j0 = nt * 8 + gc * 2;
                    const float2 cA0 = rope_tab[tA * 32 + j0];
                    const float2 cA1 = rope_tab[tA * 32 + j0 + 1];
                    const float2 cB0 = rope_tab[tB * 32 + j0];
                    const float2 cB1 = rope_tab[tB * 32 + j0 + 1];
                    const float x1a0 = acc[mt][nt][0],     x1a1 = acc[mt][nt][1];
                    const float x1b0 = acc[mt][nt][2],     x1b1 = acc[mt][nt][3];
                    const float x2a0 = acc[mt][nt + 4][0], x2a1 = acc[mt][nt + 4][1];
                    const float x2b0 = acc[mt][nt + 4][2], x2b1 = acc[mt][nt + 4][3];
                    *reinterpret_cast<__half2*>(dstA + j0) =
                        __floats2half2_rn(x1a0 * cA0.x - x2a0 * cA0.y,
                                          x1a1 * cA1.x - x2a1 * cA1.y);
                    *reinterpret_cast<__half2*>(dstA + j0 + 32) =
                        __floats2half2_rn(x2a0 * cA0.x + x1a0 * cA0.y,
                                          x2a1 * cA1.x + x1a1 * cA1.y);
                    *reinterpret_cast<__half2*>(dstB + j0) =
                        __floats2half2_rn(x1b0 * cB0.x - x2b0 * cB0.y,
                                          x1b1 * cB1.x - x2b1 * cB1.y);
                    *reinterpret_cast<__half2*>(dstB + j0 + 32) =
                        __floats2half2_rn(x2b0 * cB0.x + x1b0 * cB0.y,
                                          x2b1 * cB1.x + x1b1 * cB1.y);
                }
            } else {
                __half* dstA = v_out + (long)rowA * (N_KV * HEAD_DIM) + (head - 24) * HEAD_DIM;
                __half* dstB = dstA + 8 * (N_KV * HEAD_DIM);
                #pragma unroll
                for (int nt = 0; nt < 8; nt++) {
                    const int c = nt * 8 + gc * 2;
                    *reinterpret_cast<__half2*>(dstA + c) =
                        __floats2half2_rn(acc[mt][nt][0], acc[mt][nt][1]);
                    *reinterpret_cast<__half2*>(dstB + c) =
                        __floats2half2_rn(acc[mt][nt][2], acc[mt][nt][3]);
                }
            }
        }
        return;
    }

    if (epi == EPI_SWIGLU) {
        __half* C = (__half*)Cv;
        const int NH = N >> 1;
        #pragma unroll
        for (int mt = 0; mt < 4; mt++) {
            #pragma unroll
            for (int nt = 0; nt < 8; nt++) {
                const int row = m0 + wm * 64 + mt * 16 + gr;
                const int jcol = ((n0 + wn * 64 + nt * 8) >> 1) + gc;
                const float aA = acc[mt][nt][0], bA = acc[mt][nt][1];
                const float aB = acc[mt][nt][2], bB = acc[mt][nt][3];
                C[(long)row * NH + jcol] =
                    __float2half_rn(aA / (1.0f + __expf(-aA)) * bA);
                C[(long)(row + 8) * NH + jcol] =
                    __float2half_rn(aB / (1.0f + __expf(-aB)) * bB);
            }
        }
        return;
    }

    #pragma unroll
    for (int mt = 0; mt < 4; mt++) {
        #pragma unroll
        for (int nt = 0; nt < 8; nt++) {
            const int row = m0 + wm * 64 + mt * 16 + gr;
            const int col = n0 + wn * 64 + nt * 8 + gc * 2;
            const long offA = (long)row * N + col;
            const long offB = (long)(row + 8) * N + col;
            float2 lo = make_float2(acc[mt][nt][0], acc[mt][nt][1]);
            float2 hi = make_float2(acc[mt][nt][2], acc[mt][nt][3]);
            if (epi == EPI_RES) {
                const float* R = (const float*)Rv;
                float2 r0 = *reinterpret_cast<const float2*>(R + offA);
                float2 r1 = *reinterpret_cast<const float2*>(R + offB);
                lo.x += r0.x; lo.y += r0.y;
                hi.x += r1.x; hi.y += r1.y;
                *reinterpret_cast<float2*>((float*)Cv + offA) = lo;
                *reinterpret_cast<float2*>((float*)Cv + offB) = hi;
            } else {  // EPI_HALF
                *reinterpret_cast<__half2*>((__half*)Cv + offA) = __floats2half2_rn(lo.x, lo.y);
                *reinterpret_cast<__half2*>((__half*)Cv + offB) = __floats2half2_rn(hi.x, hi.y);
            }
        }
    }
}

// ---------------------------------------------------------------------------
// fp16 flash attention, causal GQA (exact R12)
// ---------------------------------------------------------------------------
#define QS_LDH 72
#define KS_LDH 72
#define VS_LDH 72
#define ATTN_SMEM ((128 * QS_LDH + 2 * 64 * KS_LDH + 2 * 64 * VS_LDH) * 2)

__global__ void __launch_bounds__(128, 2)
attn_h(const __half* __restrict__ qh, const __half* __restrict__ kh,
       const __half* __restrict__ vh, __half* __restrict__ o) {
    extern __shared__ __half smh[];
    __half* Qs = smh;
    __half* Kb[2] = { smh + 128 * QS_LDH, smh + 128 * QS_LDH + 64 * KS_LDH };
    __half* Vb[2] = { Kb[1] + 64 * KS_LDH, Kb[1] + 64 * KS_LDH + 64 * VS_LDH };

    const int tid  = threadIdx.x;
    const int warp = tid >> 5;
    const int lane = tid & 31;
    const int gr = lane >> 2;
    const int gc = lane & 3;
    const int wr = warp << 5;

    const int t0  = blockIdx.x << 7;
    const int bh  = blockIdx.y;
    const int b   = bh >> 4;
    const int hq  = bh & 15;
    const int kvh = hq >> 1;

    const uint32_t qsb = cvta_s(Qs);
    uint32_t ksb[2] = { cvta_s(Kb[0]), cvta_s(Kb[1]) };
    uint32_t vsb[2] = { cvta_s(Vb[0]), cvta_s(Vb[1]) };

    const int l7  = lane & 7;
    const int sel = lane >> 3;
    const uint32_t aQoff = (uint32_t)(((wr + l7 + (sel & 1) * 8) * QS_LDH + (sel >> 1) * 8) * 2);
    const uint32_t bKoff = (uint32_t)(((l7 + (sel >> 1) * 8) * KS_LDH + (sel & 1) * 8) * 2);
    const uint32_t vToff = (uint32_t)((((sel & 1) * 8 + l7) * VS_LDH + (sel >> 1) * 8) * 2);

    const int ldr = tid >> 3;
    const int ldc = (tid & 7) << 3;

    {
        #pragma unroll
        for (int p = 0; p < 8; p++) {
            const int row = ldr + p * 16;
            cp16(qsb + (uint32_t)((row * QS_LDH + ldc) * 2),
                 qh + (long)(b * SEQ + t0 + row) * D_MODEL + hq * HEAD_DIM + ldc);
        }
    }
    {
        #pragma unroll
        for (int p = 0; p < 4; p++) {
            const int row = ldr + p * 16;
            const long base = (long)(b * SEQ + row) * (N_KV * HEAD_DIM) + kvh * HEAD_DIM + ldc;
            cp16(ksb[0] + (uint32_t)((row * KS_LDH + ldc) * 2), kh + base);
            cp16(vsb[0] + (uint32_t)((row * VS_LDH + ldc) * 2), vh + base);
        }
        CP_COMMIT();
    }

    float ofrag[2][8][4];
    #pragma unroll
    for (int mt = 0; mt < 2; mt++)
        #pragma unroll
        for (int nt = 0; nt < 8; nt++)
            #pragma unroll
            for (int r = 0; r < 4; r++) ofrag[mt][nt][r] = 0.f;

    float mrow[2][2] = {{-1e30f, -1e30f}, {-1e30f, -1e30f}};
    float lrow[2][2] = {{0.f, 0.f}, {0.f, 0.f}};
    const float SC = 0.125f;

    const int ntiles = (t0 >> 6) + 2;
    for (int it = 0; it < ntiles; it++) {
        const int s0 = it << 6;
        const int cur = it & 1;

        if (it + 1 < ntiles) {
            const int nxt = cur ^ 1;
            const long roff = (long)((it + 1) << 6) * (N_KV * HEAD_DIM);
            #pragma unroll
            for (int p = 0; p < 4; p++) {
                const int row = ldr + p * 16;
                const long base = (long)(b * SEQ + row) * (N_KV * HEAD_DIM) + kvh * HEAD_DIM + ldc + roff;
                cp16(ksb[nxt] + (uint32_t)((row * KS_LDH + ldc) * 2), kh + base);
                cp16(vsb[nxt] + (uint32_t)((row * VS_LDH + ldc) * 2), vh + base);
            }
            CP_COMMIT();
            CP_WAIT1();
        } else {
            CP_WAIT0();
        }
        __syncthreads();

        float sfrag[2][8][4];
        #pragma unroll
        for (int mt = 0; mt < 2; mt++)
            #pragma unroll
            for (int nt = 0; nt < 8; nt++)
                #pragma unroll
                for (int r = 0; r < 4; r++) sfrag[mt][nt][r] = 0.f;

        #pragma unroll
        for (int ks = 0; ks < 4; ks++) {
            const uint32_t kb = (uint32_t)(ks * 16 * 2);
            uint32_t aq[2][4], bk[8][2];
            #pragma unroll
            for (int mt = 0; mt < 2; mt++)
                ldm_x4(aq[mt], qsb + aQoff + (uint32_t)(mt * 16 * QS_LDH * 2) + kb);
            #pragma unroll
            for (int np = 0; np < 4; np++) {
                uint32_t d[4];
                ldm_x4(d, ksb[cur] + bKoff + (uint32_t)(np * 16 * KS_LDH * 2) + kb);
                bk[np * 2][0]     = d[0]; bk[np * 2][1]     = d[1];
                bk[np * 2 + 1][0] = d[2]; bk[np * 2 + 1][1] = d[3];
            }
            #pragma unroll
            for (int mt = 0; mt < 2; mt++)
                #pragma unroll
                for (int nt = 0; nt < 8; nt++)
                    mma_f16(sfrag[mt][nt], aq[mt], bk[nt]);
        }

        if (it >= ntiles - 2) {
            #pragma unroll
            for (int mt = 0; mt < 2; mt++) {
                const int rA = t0 + wr + mt * 16 + gr;
                const int rB = rA + 8;
                #pragma unroll
                for (int nt = 0; nt < 8; nt++) {
                    const int cb = s0 + nt * 8 + 2 * gc;
                    if (cb     > rA) sfrag[mt][nt][0] = -1e30f;
                    if (cb + 1 > rA) sfrag[mt][nt][1] = -1e30f;
                    if (cb     > rB) sfrag[mt][nt][2] = -1e30f;
                    if (cb + 1 > rB) sfrag[mt][nt][3] = -1e30f;
                }
            }
        }

        #pragma unroll
        for (int mt = 0; mt < 2; mt++) {
            float r0 = -1e30f, r1 = -1e30f;
            #pragma unroll
            for (int nt = 0; nt < 8; nt++) {
                r0 = fmaxf(r0, fmaxf(sfrag[mt][nt][0], sfrag[mt][nt][1]));
                r1 = fmaxf(r1, fmaxf(sfrag[mt][nt][2], sfrag[mt][nt][3]));
            }
            r0 = fmaxf(r0, __shfl_xor_sync(0xffffffffu, r0, 1));
            r0 = fmaxf(r0, __shfl_xor_sync(0xffffffffu, r0, 2));
            r1 = fmaxf(r1, __shfl_xor_sync(0xffffffffu, r1, 1));
            r1 = fmaxf(r1, __shfl_xor_sync(0xffffffffu, r1, 2));

            const float mn0 = fmaxf(mrow[mt][0], r0);
            const float mn1 = fmaxf(mrow[mt][1], r1);
            const float c0 = __expf((mrow[mt][0] - mn0) * SC);
            const float c1 = __expf((mrow[mt][1] - mn1) * SC);
            lrow[mt][0] *= c0;
            lrow[mt][1] *= c1;
            #pragma unroll
            for (int nt = 0; nt < 8; nt++) {
                ofrag[mt][nt][0] *= c0; ofrag[mt][nt][1] *= c0;
                ofrag[mt][nt][2] *= c1; ofrag[mt][nt][3] *= c1;
            }
            float s0s = 0.f, s1s = 0.f;
            #pragma unroll
            for (int nt = 0; nt < 8; nt++) {
                sfrag[mt][nt][0] = __expf((sfrag[mt][nt][0] - mn0) * SC);
                sfrag[mt][nt][1] = __expf((sfrag[mt][nt][1] - mn0) * SC);
                sfrag[mt][nt][2] = __expf((sfrag[mt][nt][2] - mn1) * SC);
                sfrag[mt][nt][3] = __expf((sfrag[mt][nt][3] - mn1) * SC);
                s0s += sfrag[mt][nt][0] + sfrag[mt][nt][1];
                s1s += sfrag[mt][nt][2] + sfrag[mt][nt][3];
            }
            s0s += __shfl_xor_sync(0xffffffffu, s0s, 1);
            s0s += __shfl_xor_sync(0xffffffffu, s0s, 2);
            s1s += __shfl_xor_sync(0xffffffffu, s1s, 1);
            s1s += __shfl_xor_sync(0xffffffffu, s1s, 2);
            lrow[mt][0] += s0s;
            lrow[mt][1] += s1s;
            mrow[mt][0] = mn0;
            mrow[mt][1] = mn1;
        }

        #pragma unroll
        for (int ks = 0; ks < 4; ks++) {
            uint32_t ap[2][4];
            #pragma unroll
            for (int mt = 0; mt < 2; mt++) {
                ap[mt][0] = h2_u32(__floats2half2_rn(sfrag[mt][2 * ks][0],     sfrag[mt][2 * ks][1]));
                ap[mt][1] = h2_u32(__floats2half2_rn(sfrag[mt][2 * ks][2],     sfrag[mt][2 * ks][3]));
                ap[mt][2] = h2_u32(__floats2half2_rn(sfrag[mt][2 * ks + 1][0], sfrag[mt][2 * ks + 1][1]));
                ap[mt][3] = h2_u32(__floats2half2_rn(sfrag[mt][2 * ks + 1][2], sfrag[mt][2 * ks + 1][3]));
            }
            uint32_t bv[8][2];
            #pragma unroll
            for (int np = 0; np < 4; np++) {
                uint32_t d[4];
                ldm_x4_t(d, vsb[cur] + vToff +
                            (uint32_t)((ks * 16 * VS_LDH + np * 16) * 2));
                bv[np * 2][0]     = d[0]; bv[np * 2][1]     = d[1];
                bv[np * 2 + 1][0] = d[2]; bv[np * 2 + 1][1] = d[3];
            }
            #pragma unroll
            for (int mt = 0; mt < 2; mt++)
                #pragma unroll
                for (int nt = 0; nt < 8; nt++)
                    mma_f16(ofrag[mt][nt], ap[mt], bv[nt]);
        }
        __syncthreads();
    }

    #pragma unroll
    for (int mt = 0; mt < 2; mt++) {
        const int rowA = t0 + wr + mt * 16 + gr;
        const int rowB = rowA + 8;
        const float il0 = 1.0f / lrow[mt][0];
        const float il1 = 1.0f / lrow[mt][1];
        #pragma unroll
        for (int nt = 0; nt < 8; nt++) {
            const int col = hq * HEAD_DIM + nt * 8 + 2 * gc;
            *reinterpret_cast<__half2*>(o + (long)(b * SEQ + rowA) * D_MODEL + col) =
                __floats2half2_rn(ofrag[mt][nt][0] * il0, ofrag[mt][nt][1] * il0);
            *reinterpret_cast<__half2*>(o + (long)(b * SEQ + rowB) * D_MODEL + col) =
                __floats2half2_rn(ofrag[mt][nt][2] * il1, ofrag[mt][nt][3] * il1);
        }
    }
}

// ---------------------------------------------------------------------------
// Fused prep: 7 weight transposes + rope table, ONE launch.
// R17 fix: rope segment = one (t,j) element per thread (256 blocks),
// single double-precision exp per thread (bit-identical to rope_tab_fill).
// ---------------------------------------------------------------------------
#define SEG_WQ   0
#define SEG_WK   1024
#define SEG_WV   1536
#define SEG_WO   2048
#define SEG_W1   3072
#define SEG_W2   7168
#define SEG_W3   11264
#define SEG_ROPE 15360
#define ROPE_BLOCKS ((SEQ * 32) / 256)          // 256 blocks
#define PREP_BLOCKS (SEG_ROPE + ROPE_BLOCKS)

__device__ __forceinline__ void tr_tile(const float* __restrict__ in,
                                        __half* __restrict__ out,
                                        int R, int C, int stride, int roff,
                                        int cx, int ry) {
    __shared__ float t[32][33];
    const int c0 = cx << 5, r0 = ry << 5;
    #pragma unroll
    for (int dy = 0; dy < 32; dy += 8) {
        t[threadIdx.y + dy][threadIdx.x] =
            in[(long)(r0 + threadIdx.y + dy) * C + c0 + threadIdx.x];
    }
    __syncthreads();
    #pragma unroll
    for (int dy = 0; dy < 32; dy += 8) {
        out[(long)((c0 + threadIdx.y + dy) * stride + roff) * R + r0 + threadIdx.x] =
            __float2half_rn(t[threadIdx.x][threadIdx.y + dy]);
    }
}

__global__ void prep_kernel(const float* __restrict__ wq, const float* __restrict__ wk,
                            const float* __restrict__ wv, const float* __restrict__ wo,
                            const float* __restrict__ w1, const float* __restrict__ w2,
                            const float* __restrict__ w3,
                            __half* __restrict__ wqkvT, __half* __restrict__ woT,
                            __half* __restrict__ w12T, __half* __restrict__ w3T,
                            float2* __restrict__ ropeT) {
    const int bid = blockIdx.x;
    if (bid < SEG_WK) {
        const int u = bid - SEG_WQ;
        tr_tile(wq, wqkvT, D_MODEL, D_MODEL, 1, 0, u & 31, u >> 5);
    } else if (bid < SEG_WV) {
        const int u = bid - SEG_WK;
        tr_tile(wk, wqkvT + 1024 * D_MODEL, D_MODEL, 512, 1, 0, u & 15, u >> 4);
    } else if (bid < SEG_WO) {
        const int u = bid - SEG_WV;
        tr_tile(wv, wqkvT + 1536 * D_MODEL, D_MODEL, 512, 1, 0, u & 15, u >> 4);
    } else if (bid < SEG_W1) {
        const int u = bid - SEG_WO;
        tr_tile(wo, woT, D_MODEL, D_MODEL, 1, 0, u & 31, u >> 5);
    } else if (bid < SEG_W2) {
        const int u = bid - SEG_W1;
        tr_tile(w1, w12T, D_MODEL, HIDDEN, 2, 0, u & 127, u >> 7);
    } else if (bid < SEG_W3) {
        const int u = bid - SEG_W2;
        tr_tile(w2, w12T, D_MODEL, HIDDEN, 2, 1, u & 127, u >> 7);
    } else if (bid < SEG_ROPE) {
        const int u = bid - SEG_W3;
        tr_tile(w3, w3T, HIDDEN, D_MODEL, 1, 0, u & 31, u >> 5);
    } else {
        // rope: one (t, j) element per thread
        const int idx = (bid - SEG_ROPE) * 256 + threadIdx.y * 32 + threadIdx.x;
        const int t = idx >> 5;
        const int j = idx & 31;
        float inv = (float)exp(-(double)j / 32.0 * 9.210340371976184);
        float fr = (float)t * inv;
        ropeT[idx] = make_float2(cosf(fr), sinf(fr));
    }
}

// ---------------------------------------------------------------------------
// RMSNorm: fp32 in, half out
// ---------------------------------------------------------------------------
__global__ void rmsnorm_h(const float* __restrict__ x,
                          const float* __restrict__ g,
                          __half* __restrict__ out) {
    const int row = blockIdx.x;
    const int tid = threadIdx.x;
    const float* xr = x + (long)row * D_MODEL;
    float4 v = *reinterpret_cast<const float4*>(xr + tid * 4);
    float s = v.x * v.x + v.y * v.y + v.z * v.z + v.w * v.w;

    #pragma unroll
    for (int off = 16; off > 0; off >>= 1)
        s += __shfl_xor_sync(0xffffffffu, s, off);

    __shared__ float red[8];
    if ((tid & 31) == 0) red[tid >> 5] = s;
    __syncthreads();
    float total;
    {
        float t = (tid < 8) ? red[tid] : 0.f;
        #pragma unroll
        for (int off = 4; off > 0; off >>= 1)
            t += __shfl_xor_sync(0xffffffffu, t, off);
        __shared__ float bc;
        if (tid == 0) bc = t;
        __syncthreads();
        total = bc;
    }
    float inv = rsqrtf(total * (1.0f / D_MODEL) + 1e-6f);
    float4 gv = *reinterpret_cast<const float4*>(g + tid * 4);
    uint2 pk;
    pk.x = h2_u32(__floats2half2_rn(v.x * inv * gv.x, v.y * inv * gv.y));
    pk.y = h2_u32(__floats2half2_rn(v.z * inv * gv.z, v.w * inv * gv.w));
    *reinterpret_cast<uint2*>(out + (long)row * D_MODEL + tid * 4) = pk;
}

// ---------------------------------------------------------------------------
// Launch
// ---------------------------------------------------------------------------
extern "C" void kernel_launch(void* const* d_in, const int* in_sizes, int n_in,
                              void* d_out, int out_size) {
    const float* x  = (const float*)d_in[0];
    const float* g1 = (const float*)d_in[1];
    const float* g2 = (const float*)d_in[2];
    const float* wq = (const float*)d_in[3];
    const float* wk = (const float*)d_in[4];
    const float* wv = (const float*)d_in[5];
    const float* wo = (const float*)d_in[6];
    const float* w1 = (const float*)d_in[7];
    const float* w2 = (const float*)d_in[8];
    const float* w3 = (const float*)d_in[9];
    float* out = (float*)d_out;

    __half *h, *qh, *kh, *vh, *ao, *h2, *a2;
    __half *wqkvT, *woT, *w12T, *w3T;
    float2* ropeT;
    cudaGetSymbolAddress((void**)&h,   g_h);
    cudaGetSymbolAddress((void**)&qh,  g_qh);
    cudaGetSymbolAddress((void**)&kh,  g_kh);
    cudaGetSymbolAddress((void**)&vh,  g_vh);
    cudaGetSymbolAddress((void**)&ao,  g_ao);
    cudaGetSymbolAddress((void**)&h2,  g_h2);
    cudaGetSymbolAddress((void**)&a2,  g_a2);
    cudaGetSymbolAddress((void**)&ropeT, g_rope);
    cudaGetSymbolAddress((void**)&wqkvT, g_wqkvT);
    cudaGetSymbolAddress((void**)&woT,  g_woT);
    cudaGetSymbolAddress((void**)&w12T, g_w12T);
    cudaGetSymbolAddress((void**)&w3T,  g_w3T);

    cudaFuncSetAttribute(hgemm, cudaFuncAttributeMaxDynamicSharedMemorySize,
                         GEMM_SMEM_BYTES);
    cudaFuncSetAttribute(attn_h, cudaFuncAttributeMaxDynamicSharedMemorySize,
                         ATTN_SMEM);

    // 0. all weight transposes + rope table, one launch
    prep_kernel<<<PREP_BLOCKS, dim3(32, 8)>>>(wq, wk, wv, wo, w1, w2, w3,
                                              wqkvT, woT, w12T, w3T, ropeT);

    // 1. h = rmsnorm(x, g1)
    rmsnorm_h<<<BT, 256>>>(x, g1, h);

    // 2. fused qkv projection + RoPE + half conversion
    hgemm<<<dim3(QKV_N / 128, BT / 128), 128, GEMM_SMEM_BYTES>>>(
        h, wqkvT, nullptr, nullptr, BT, QKV_N, D_MODEL, EPI_ROPE,
        qh, kh, vh, ropeT);

    // 3. fp16 attention -> ao
    attn_h<<<dim3(SEQ / 128, BATCH * N_HEADS), 128, ATTN_SMEM>>>(qh, kh, vh, ao);

    // 4. out = ao @ wo + x
    hgemm<<<dim3(D_MODEL / 128, BT / 128), 128, GEMM_SMEM_BYTES>>>(
        ao, woT, x, out, BT, D_MODEL, D_MODEL, EPI_RES,
        nullptr, nullptr, nullptr, nullptr);

    // 5. h2 = rmsnorm(out, g2)
    rmsnorm_h<<<BT, 256>>>(out, g2, h2);

    // 6. fused FFN-up: a2 = silu(h2 @ w1) * (h2 @ w2)
    hgemm<<<dim3((2 * HIDDEN) / 128, BT / 128), 128, GEMM_SMEM_BYTES>>>(
        h2, w12T, nullptr, a2, BT, 2 * HIDDEN, D_MODEL, EPI_SWIGLU,
        nullptr, nullptr, nullptr, nullptr);

    // 7. out += a2 @ w3
    hgemm<<<dim3(D_MODEL / 128, BT / 128), 128, GEMM_SMEM_BYTES>>>(
        a2, w3T, out, out, BT, D_MODEL, HIDDEN, EPI_RES,
        nullptr, nullptr, nullptr, nullptr);
}